// round 2
// baseline (speedup 1.0000x reference)
#include <cuda_runtime.h>

// Shapes fixed by the reference.
#define BB 512     // batch
#define HH 1024    // hidden
#define II 256     // input / output feature
#define LL 256     // rollout length
#define G3 3072    // 3*HH
#define NG 4096    // gate GEMM output width (4*HH)
#define N5 4352    // NG + II (appended W_head rows -> y)
#define KK 1024    // GEMM K (hidden)
#define NCTAS 136  // 4 m-tiles x 34 n-tiles (128x128 tiles)
#define TPB 256

typedef unsigned long long ull;

// ---------------------------------------------------------------------------
// Static device scratch (no allocations allowed).
// ---------------------------------------------------------------------------
__device__ float g_h[BB * HH];       // hidden state
__device__ float g_G[BB * NG];       // per-step gate pre-activations
__device__ float g_W5[N5 * KK];      // folded weights, steps >= 1
__device__ float g_W50[N5 * KK];     // folded weights, step 0 (x = 0)
__device__ float g_b5[NG];           // gate biases, steps >= 1
__device__ float g_b50[NG];          // gate biases, step 0
__device__ unsigned g_bar;           // grid barrier counter

// ---------------------------------------------------------------------------
// f32x2 packed-FMA helpers (Blackwell sm_103a)
// ---------------------------------------------------------------------------
__device__ __forceinline__ ull dup2(float x) {
    ull r; asm("mov.b64 %0, {%1, %1};" : "=l"(r) : "f"(x)); return r;
}
__device__ __forceinline__ void ffma2(ull& d, ull a, ull b) {
    asm("fma.rn.f32x2 %0, %1, %2, %0;" : "+l"(d) : "l"(a), "l"(b));
}
__device__ __forceinline__ void unpk2(ull v, float& lo, float& hi) {
    asm("mov.b64 {%0, %1}, %2;" : "=f"(lo), "=f"(hi) : "l"(v));
}

// ---------------------------------------------------------------------------
// Init: h = context, reset barrier.
// ---------------------------------------------------------------------------
__global__ void init_state(const float* __restrict__ ctx) {
    int i = blockIdx.x * blockDim.x + threadIdx.x;
    if (i < BB * HH) g_h[i] = ctx[i];
    if (i == 0) g_bar = 0u;
}

// ---------------------------------------------------------------------------
// Bias build:
//   bc[n] = b_ih[n] + W_ih[n,:] . b_head        (n < 3072)
//   b5    = [b_hh_rz + bc_rz ; bc_n ; b_hh_n]
//   b5_0  = [b_ih_rz + b_hh_rz ; b_ih_n ; b_hh_n]
// ---------------------------------------------------------------------------
__global__ void build_bias(const float* __restrict__ Wih,
                           const float* __restrict__ bih,
                           const float* __restrict__ bhh,
                           const float* __restrict__ bhead) {
    int j = blockIdx.x * blockDim.x + threadIdx.x;
    if (j >= NG) return;
    float v0, v1;
    if (j < 2048)      v0 = bih[j] + bhh[j];
    else if (j < G3)   v0 = bih[j];
    else               v0 = bhh[j - 1024];
    if (j < G3) {
        float d = 0.0f;
        const float* wr = Wih + (size_t)j * II;
        for (int i = 0; i < II; ++i) d += wr[i] * bhead[i];
        float bc = bih[j] + d;
        v1 = (j < 2048) ? (bhh[j] + bc) : bc;
    } else {
        v1 = bhh[j - 1024];
    }
    g_b50[j] = v0;
    g_b5[j]  = v1;
}

// ---------------------------------------------------------------------------
// Assemble the non-GEMM blocks of W5 / W5_0:
//   W5_0 = [W_hh_rz ; 0 ; W_hh_n ; W_head]
//   W5 rows >= 3072:  [W_hh_n ; W_head]   (rows < 3072 written by wc_gemm)
// ---------------------------------------------------------------------------
__global__ void assemble_w(const float* __restrict__ Whh,
                           const float* __restrict__ Whead) {
    for (int idx = blockIdx.x * blockDim.x + threadIdx.x;
         idx < N5 * KK; idx += gridDim.x * blockDim.x) {
        int n = idx >> 10;      // / KK
        float v;
        if (n < 2048)      v = Whh[idx];
        else if (n < G3)   v = 0.0f;
        else if (n < NG)   v = Whh[idx - 1024 * KK];
        else               v = Whead[idx - NG * KK];
        g_W50[idx] = v;
        if (n >= G3) g_W5[idx] = v;
    }
}

// ---------------------------------------------------------------------------
// wc_gemm: W5[n,k] for n < 3072:
//   Wc = W_ih @ W_head   ([3072,256] @ [256,1024])
//   W5[n,k] = Wc[n,k] + (n < 2048 ? W_hh[n,k] : 0)
// 64x64 tile, BK=16, 256 threads, 4x4 microtile.
// ---------------------------------------------------------------------------
__global__ void __launch_bounds__(256)
wc_gemm(const float* __restrict__ Wih,
        const float* __restrict__ Whh,
        const float* __restrict__ Whead) {
    __shared__ __align__(16) float As[16][68];
    __shared__ __align__(16) float Bs[16][68];
    const int tid = threadIdx.x;
    const int n0 = blockIdx.y * 64;
    const int k0 = blockIdx.x * 64;
    const int ty = tid >> 4, tx = tid & 15;

    float acc[4][4] = {};
    for (int i0 = 0; i0 < II; i0 += 16) {
        {   // A tile (transpose): Wih[n0+row][i0+ic..+3]
            int row = tid >> 2, ic = (tid & 3) * 4;
            float4 av = *reinterpret_cast<const float4*>(
                Wih + (size_t)(n0 + row) * II + i0 + ic);
            As[ic + 0][row] = av.x; As[ic + 1][row] = av.y;
            As[ic + 2][row] = av.z; As[ic + 3][row] = av.w;
        }
        {   // B tile (direct): Whead[i0+r][k0+kc..+3]
            int r = tid >> 4, kc = (tid & 15) * 4;
            float4 bv = *reinterpret_cast<const float4*>(
                Whead + (size_t)(i0 + r) * KK + k0 + kc);
            *reinterpret_cast<float4*>(&Bs[r][kc]) = bv;
        }
        __syncthreads();
#pragma unroll
        for (int i = 0; i < 16; ++i) {
            float a[4], b[4];
#pragma unroll
            for (int u = 0; u < 4; ++u) a[u] = As[i][ty * 4 + u];
#pragma unroll
            for (int u = 0; u < 4; ++u) b[u] = Bs[i][tx * 4 + u];
#pragma unroll
            for (int r = 0; r < 4; ++r)
#pragma unroll
                for (int c = 0; c < 4; ++c) acc[r][c] = fmaf(a[r], b[c], acc[r][c]);
        }
        __syncthreads();
    }
#pragma unroll
    for (int r = 0; r < 4; ++r) {
        int n = n0 + ty * 4 + r;
#pragma unroll
        for (int c = 0; c < 4; ++c) {
            int k = k0 + tx * 4 + c;
            float w = acc[r][c];
            if (n < 2048) w += Whh[(size_t)n * KK + k];
            g_W5[(size_t)n * KK + k] = w;
        }
    }
}

// ---------------------------------------------------------------------------
// Grid barrier (all NCTAS CTAs co-resident: 136 <= 148 SMs, 1 CTA/SM).
// ---------------------------------------------------------------------------
__device__ __forceinline__ void grid_barrier(unsigned& phase) {
    __syncthreads();
    phase += NCTAS;
    if (threadIdx.x == 0) {
        __threadfence();
        atomicAdd(&g_bar, 1u);
        while (*(volatile unsigned*)&g_bar < phase) { }
        __threadfence();
    }
    __syncthreads();
}

// ---------------------------------------------------------------------------
// Persistent rollout. Each CTA owns one 128x128 output tile of
//   G5 = h @ W5^T   (M=512, N=4352, K=1024)
// n-tiles 0..31 -> g_G (gate preacts); n-tiles 32..33 -> y_{t-1} into d_out.
// Iteration t in [0,256]:
//   GEMM(h_t) ; barrier ; gates -> h_{t+1} ; barrier
// t=0 uses W5_0 (x=0); t=256 computes only the y part (y_255).
// ---------------------------------------------------------------------------
__global__ void __launch_bounds__(TPB, 1)
rollout(float* __restrict__ out, const float* __restrict__ b_head) {
    __shared__ __align__(16) float As[2][16][132];
    __shared__ __align__(16) float Bs[2][16][132];

    const int tid = threadIdx.x;
    const int cta = blockIdx.x;
    const int m0 = (cta & 3) * 128;
    const int n0 = (cta >> 2) * 128;
    const bool is_y = (n0 >= NG);
    const int ty = tid >> 4;      // 0..15 -> rows ty*8..+7
    const int tx = tid & 15;      // 0..15 -> cols tx*8..+7

    const int ar = tid >> 2;          // 0..63 (load row, +64 for second half)
    const int ac = (tid & 3) * 4;     // 0..12 (load k offset)

    unsigned phase = 0;

    for (int t = 0; t <= LL; ++t) {
        const float* W = (t == 0) ? g_W50 : g_W5;
        const bool active = (t < LL) ? !(t == 0 && is_y) : is_y;

        if (active) {
            ull acc[4][8];
#pragma unroll
            for (int i = 0; i < 4; ++i)
#pragma unroll
                for (int j = 0; j < 8; ++j) acc[i][j] = 0ull;

            const float* Ab = g_h + (size_t)m0 * KK;
            const float* Bb = W + (size_t)n0 * KK;

            float4 pa0, pa1, pb0, pb1;
            pa0 = *reinterpret_cast<const float4*>(Ab + (size_t)ar * KK + ac);
            pa1 = *reinterpret_cast<const float4*>(Ab + (size_t)(ar + 64) * KK + ac);
            pb0 = *reinterpret_cast<const float4*>(Bb + (size_t)ar * KK + ac);
            pb1 = *reinterpret_cast<const float4*>(Bb + (size_t)(ar + 64) * KK + ac);
            {
                As[0][ac + 0][ar] = pa0.x; As[0][ac + 1][ar] = pa0.y;
                As[0][ac + 2][ar] = pa0.z; As[0][ac + 3][ar] = pa0.w;
                As[0][ac + 0][ar + 64] = pa1.x; As[0][ac + 1][ar + 64] = pa1.y;
                As[0][ac + 2][ar + 64] = pa1.z; As[0][ac + 3][ar + 64] = pa1.w;
                Bs[0][ac + 0][ar] = pb0.x; Bs[0][ac + 1][ar] = pb0.y;
                Bs[0][ac + 2][ar] = pb0.z; Bs[0][ac + 3][ar] = pb0.w;
                Bs[0][ac + 0][ar + 64] = pb1.x; Bs[0][ac + 1][ar + 64] = pb1.y;
                Bs[0][ac + 2][ar + 64] = pb1.z; Bs[0][ac + 3][ar + 64] = pb1.w;
            }
            __syncthreads();

            for (int kt = 0; kt < 64; ++kt) {
                const int cur = kt & 1;
                if (kt < 63) {
                    const int ko = (kt + 1) * 16 + ac;
                    pa0 = *reinterpret_cast<const float4*>(Ab + (size_t)ar * KK + ko);
                    pa1 = *reinterpret_cast<const float4*>(Ab + (size_t)(ar + 64) * KK + ko);
                    pb0 = *reinterpret_cast<const float4*>(Bb + (size_t)ar * KK + ko);
                    pb1 = *reinterpret_cast<const float4*>(Bb + (size_t)(ar + 64) * KK + ko);
                }
#pragma unroll
                for (int k = 0; k < 16; ++k) {
                    const double* arp = reinterpret_cast<const double*>(&As[cur][k][ty * 8]);
                    ull A0 = __double_as_longlong(arp[0]);
                    ull A1 = __double_as_longlong(arp[1]);
                    ull A2 = __double_as_longlong(arp[2]);
                    ull A3 = __double_as_longlong(arp[3]);
                    const float* brp = &Bs[cur][k][tx * 8];
                    float4 bf0 = *reinterpret_cast<const float4*>(brp);
                    float4 bf1 = *reinterpret_cast<const float4*>(brp + 4);
                    ull B0 = dup2(bf0.x), B1 = dup2(bf0.y), B2 = dup2(bf0.z), B3 = dup2(bf0.w);
                    ull B4 = dup2(bf1.x), B5 = dup2(bf1.y), B6 = dup2(bf1.z), B7 = dup2(bf1.w);
                    ffma2(acc[0][0], A0, B0); ffma2(acc[0][1], A0, B1);
                    ffma2(acc[0][2], A0, B2); ffma2(acc[0][3], A0, B3);
                    ffma2(acc[0][4], A0, B4); ffma2(acc[0][5], A0, B5);
                    ffma2(acc[0][6], A0, B6); ffma2(acc[0][7], A0, B7);
                    ffma2(acc[1][0], A1, B0); ffma2(acc[1][1], A1, B1);
                    ffma2(acc[1][2], A1, B2); ffma2(acc[1][3], A1, B3);
                    ffma2(acc[1][4], A1, B4); ffma2(acc[1][5], A1, B5);
                    ffma2(acc[1][6], A1, B6); ffma2(acc[1][7], A1, B7);
                    ffma2(acc[2][0], A2, B0); ffma2(acc[2][1], A2, B1);
                    ffma2(acc[2][2], A2, B2); ffma2(acc[2][3], A2, B3);
                    ffma2(acc[2][4], A2, B4); ffma2(acc[2][5], A2, B5);
                    ffma2(acc[2][6], A2, B6); ffma2(acc[2][7], A2, B7);
                    ffma2(acc[3][0], A3, B0); ffma2(acc[3][1], A3, B1);
                    ffma2(acc[3][2], A3, B2); ffma2(acc[3][3], A3, B3);
                    ffma2(acc[3][4], A3, B4); ffma2(acc[3][5], A3, B5);
                    ffma2(acc[3][6], A3, B6); ffma2(acc[3][7], A3, B7);
                }
                if (kt < 63) {
                    const int nxt = cur ^ 1;
                    As[nxt][ac + 0][ar] = pa0.x; As[nxt][ac + 1][ar] = pa0.y;
                    As[nxt][ac + 2][ar] = pa0.z; As[nxt][ac + 3][ar] = pa0.w;
                    As[nxt][ac + 0][ar + 64] = pa1.x; As[nxt][ac + 1][ar + 64] = pa1.y;
                    As[nxt][ac + 2][ar + 64] = pa1.z; As[nxt][ac + 3][ar + 64] = pa1.w;
                    Bs[nxt][ac + 0][ar] = pb0.x; Bs[nxt][ac + 1][ar] = pb0.y;
                    Bs[nxt][ac + 2][ar] = pb0.z; Bs[nxt][ac + 3][ar] = pb0.w;
                    Bs[nxt][ac + 0][ar + 64] = pb1.x; Bs[nxt][ac + 1][ar + 64] = pb1.y;
                    Bs[nxt][ac + 2][ar + 64] = pb1.z; Bs[nxt][ac + 3][ar + 64] = pb1.w;
                    __syncthreads();
                }
            }

            // Epilogue
            if (!is_y) {
                float* Cp = g_G + (size_t)(m0 + ty * 8) * NG + n0 + tx * 8;
#pragma unroll
                for (int i2 = 0; i2 < 4; ++i2)
#pragma unroll
                    for (int j = 0; j < 8; ++j) {
                        float lo, hi;
                        unpk2(acc[i2][j], lo, hi);
                        Cp[(size_t)(2 * i2) * NG + j] = lo;
                        Cp[(size_t)(2 * i2 + 1) * NG + j] = hi;
                    }
            } else if (t >= 1) {
                const int c0 = (n0 - NG) + tx * 8;
                float* Yp = out + (size_t)(t - 1) * BB * II
                                + (size_t)(m0 + ty * 8) * II + c0;
                float bh[8];
#pragma unroll
                for (int j = 0; j < 8; ++j) bh[j] = __ldg(b_head + c0 + j);
#pragma unroll
                for (int i2 = 0; i2 < 4; ++i2)
#pragma unroll
                    for (int j = 0; j < 8; ++j) {
                        float lo, hi;
                        unpk2(acc[i2][j], lo, hi);
                        Yp[(size_t)(2 * i2) * II + j] = lo + bh[j];
                        Yp[(size_t)(2 * i2 + 1) * II + j] = hi + bh[j];
                    }
            }
        }

        if (t == LL) break;

        grid_barrier(phase);

        {   // GRU gates: h <- (1-z)*n + z*h
            const float* bias = (t == 0) ? g_b50 : g_b5;
            for (int i = cta * TPB + tid; i < BB * HH; i += NCTAS * TPB) {
                int b = i >> 10, j = i & 1023;
                const float* Gr = g_G + (size_t)b * NG;
                float rp  = Gr[j]        + __ldg(bias + j);
                float zp  = Gr[1024 + j] + __ldg(bias + 1024 + j);
                float gin = Gr[2048 + j] + __ldg(bias + 2048 + j);
                float ghn = Gr[3072 + j] + __ldg(bias + 3072 + j);
                float r = 1.0f / (1.0f + expf(-rp));
                float z = 1.0f / (1.0f + expf(-zp));
                float n = tanhf(gin + r * ghn);
                g_h[i] = (1.0f - z) * n + z * g_h[i];
            }
        }

        grid_barrier(phase);
    }
}

// ---------------------------------------------------------------------------
// 5 graph nodes total: init, bias, assemble, wc_gemm, rollout.
// ---------------------------------------------------------------------------
extern "C" void kernel_launch(void* const* d_in, const int* in_sizes, int n_in,
                              void* d_out, int out_size) {
    const float *ctx = nullptr, *Wih = nullptr, *Whh = nullptr,
                *bih = nullptr, *bhh = nullptr, *Whead = nullptr, *bhead = nullptr;
    int b3_seen = 0;
    for (int i = 0; i < n_in; i++) {
        long sz = in_sizes[i];
        const float* p = (const float*)d_in[i];
        if (sz == (long)BB * HH) ctx = p;
        else if (sz == (long)G3 * II) Wih = p;
        else if (sz == (long)G3 * HH) Whh = p;
        else if (sz == (long)G3) { if (b3_seen++ == 0) bih = p; else bhh = p; }
        else if (sz == (long)II * HH) Whead = p;
        else if (sz == (long)II) bhead = p;
    }
    float* out = (float*)d_out;

    init_state<<<(BB * HH + 255) / 256, 256>>>(ctx);
    build_bias<<<NG / 256, 256>>>(Wih, bih, bhh, bhead);
    assemble_w<<<512, 256>>>(Whh, Whead);
    wc_gemm<<<dim3(KK / 64, G3 / 64), 256>>>(Wih, Whh, Whead);
    rollout<<<NCTAS, TPB>>>(out, bhead);

    (void)out_size;
    (void)n_in;
}

// round 5
// speedup vs baseline: 1.5009x; 1.5009x over previous
#include <cuda_runtime.h>
#include <cuda_bf16.h>
#include <cstdint>

// Shapes fixed by the reference.
#define BB 512     // batch
#define HH 1024    // hidden
#define II 256     // input / output feature
#define LL 256     // rollout length
#define G3 3072    // 3*HH
#define NG 4096    // gate GEMM output width (4*HH)
#define N5 4352    // NG + II (appended W_head rows -> y)
#define KK 1024    // GEMM K
#define NCTAS 136  // 4 m-tiles x 34 n-tiles (128x128)
#define TPB 256

#define KC 32                    // bf16 K elements per chunk
#define NCHUNK (KK / KC)         // 32
#define ROWB 80                  // padded smem row bytes (40 halves)
#define BUFB (128 * ROWB)        // 10240 B per 128x32 tile
#define STAGE_BYTES (4 * BUFB)   // Ah, Al, Bh, Bl
#define SMEM_DYN (2 * STAGE_BYTES)

typedef unsigned long long ull;
typedef __nv_bfloat16 bf16;

// ---------------------------------------------------------------------------
// Static device scratch.
// ---------------------------------------------------------------------------
__device__ float g_h[BB * HH];          // fp32 master hidden state
__device__ bf16  g_hbh[BB * HH];        // bf16 hi part of h
__device__ bf16  g_hbl[BB * HH];        // bf16 lo part of h
__device__ float g_G[BB * NG];          // gate pre-activations
__device__ float g_W5[N5 * KK];         // folded weights (fp32, setup)
__device__ float g_W50[N5 * KK];        // step-0 folded weights
__device__ bf16  g_Wbh[N5 * KK], g_Wbl[N5 * KK];
__device__ bf16  g_W0bh[N5 * KK], g_W0bl[N5 * KK];
__device__ float g_b5[NG];
__device__ float g_b50[NG];
__device__ unsigned g_bar;

// ---------------------------------------------------------------------------
// PTX helpers (all base-ISA: sm_80-era, valid on compute_103)
// ---------------------------------------------------------------------------
__device__ __forceinline__ uint32_t smem_u32(const void* p) {
    uint32_t a;
    asm("{ .reg .u64 t; cvta.to.shared.u64 t, %1; cvt.u32.u64 %0, t; }" : "=r"(a) : "l"(p));
    return a;
}

__device__ __forceinline__ void ldsm_x4(uint32_t* r, uint32_t addr) {
    asm volatile("ldmatrix.sync.aligned.m8n8.x4.shared.b16 {%0,%1,%2,%3}, [%4];"
                 : "=r"(r[0]), "=r"(r[1]), "=r"(r[2]), "=r"(r[3]) : "r"(addr));
}
__device__ __forceinline__ void mma_bf16(float* d, const uint32_t* a,
                                         uint32_t b0, uint32_t b1) {
    asm volatile(
        "mma.sync.aligned.m16n8k16.row.col.f32.bf16.bf16.f32 "
        "{%0,%1,%2,%3}, {%4,%5,%6,%7}, {%8,%9}, {%0,%1,%2,%3};"
        : "+f"(d[0]), "+f"(d[1]), "+f"(d[2]), "+f"(d[3])
        : "r"(a[0]), "r"(a[1]), "r"(a[2]), "r"(a[3]), "r"(b0), "r"(b1));
}

#define CP_ASYNC16(smem, gptr) \
    asm volatile("cp.async.cg.shared.global [%0], [%1], 16;" :: "r"(smem), "l"(gptr))
#define CP_COMMIT() asm volatile("cp.async.commit_group;" ::: "memory")
template <int N>
__device__ __forceinline__ void cp_wait() {
    asm volatile("cp.async.wait_group %0;" :: "n"(N) : "memory");
}

// ---------------------------------------------------------------------------
// Setup kernels
// ---------------------------------------------------------------------------
__global__ void init_state(const float* __restrict__ ctx) {
    int i = blockIdx.x * blockDim.x + threadIdx.x;
    if (i < BB * HH) {
        float v = ctx[i];
        g_h[i] = v;
        bf16 h0 = __float2bfloat16(v);
        g_hbh[i] = h0;
        g_hbl[i] = __float2bfloat16(v - __bfloat162float(h0));
    }
    if (i == 0) g_bar = 0u;
}

__global__ void build_bias(const float* __restrict__ Wih,
                           const float* __restrict__ bih,
                           const float* __restrict__ bhh,
                           const float* __restrict__ bhead) {
    int j = blockIdx.x * blockDim.x + threadIdx.x;
    if (j >= NG) return;
    float v0, v1;
    if (j < 2048)      v0 = bih[j] + bhh[j];
    else if (j < G3)   v0 = bih[j];
    else               v0 = bhh[j - 1024];
    if (j < G3) {
        float d = 0.0f;
        const float* wr = Wih + (size_t)j * II;
        for (int i = 0; i < II; ++i) d += wr[i] * bhead[i];
        float bc = bih[j] + d;
        v1 = (j < 2048) ? (bhh[j] + bc) : bc;
    } else {
        v1 = bhh[j - 1024];
    }
    g_b50[j] = v0;
    g_b5[j]  = v1;
}

__global__ void assemble_w(const float* __restrict__ Whh,
                           const float* __restrict__ Whead) {
    for (int idx = blockIdx.x * blockDim.x + threadIdx.x;
         idx < N5 * KK; idx += gridDim.x * blockDim.x) {
        int n = idx >> 10;
        float v;
        if (n < 2048)      v = Whh[idx];
        else if (n < G3)   v = 0.0f;
        else if (n < NG)   v = Whh[idx - 1024 * KK];
        else               v = Whead[idx - NG * KK];
        g_W50[idx] = v;
        if (n >= G3) g_W5[idx] = v;
    }
}

__global__ void __launch_bounds__(256)
wc_gemm(const float* __restrict__ Wih,
        const float* __restrict__ Whh,
        const float* __restrict__ Whead) {
    __shared__ __align__(16) float As[16][68];
    __shared__ __align__(16) float Bs[16][68];
    const int tid = threadIdx.x;
    const int n0 = blockIdx.y * 64;
    const int k0 = blockIdx.x * 64;
    const int ty = tid >> 4, tx = tid & 15;

    float acc[4][4] = {};
    for (int i0 = 0; i0 < II; i0 += 16) {
        {
            int row = tid >> 2, ic = (tid & 3) * 4;
            float4 av = *reinterpret_cast<const float4*>(Wih + (size_t)(n0 + row) * II + i0 + ic);
            As[ic + 0][row] = av.x; As[ic + 1][row] = av.y;
            As[ic + 2][row] = av.z; As[ic + 3][row] = av.w;
        }
        {
            int r = tid >> 4, kc = (tid & 15) * 4;
            float4 bv = *reinterpret_cast<const float4*>(Whead + (size_t)(i0 + r) * KK + k0 + kc);
            *reinterpret_cast<float4*>(&Bs[r][kc]) = bv;
        }
        __syncthreads();
#pragma unroll
        for (int i = 0; i < 16; ++i) {
            float a[4], b[4];
#pragma unroll
            for (int u = 0; u < 4; ++u) a[u] = As[i][ty * 4 + u];
#pragma unroll
            for (int u = 0; u < 4; ++u) b[u] = Bs[i][tx * 4 + u];
#pragma unroll
            for (int r = 0; r < 4; ++r)
#pragma unroll
                for (int c = 0; c < 4; ++c) acc[r][c] = fmaf(a[r], b[c], acc[r][c]);
        }
        __syncthreads();
    }
#pragma unroll
    for (int r = 0; r < 4; ++r) {
        int n = n0 + ty * 4 + r;
#pragma unroll
        for (int c = 0; c < 4; ++c) {
            int k = k0 + tx * 4 + c;
            float w = acc[r][c];
            if (n < 2048) w += Whh[(size_t)n * KK + k];
            g_W5[(size_t)n * KK + k] = w;
        }
    }
}

__global__ void split_w() {
    for (int idx = blockIdx.x * blockDim.x + threadIdx.x;
         idx < N5 * KK; idx += gridDim.x * blockDim.x) {
        float w = g_W5[idx];
        bf16 wh = __float2bfloat16(w);
        g_Wbh[idx] = wh;
        g_Wbl[idx] = __float2bfloat16(w - __bfloat162float(wh));
        float w0 = g_W50[idx];
        bf16 w0h = __float2bfloat16(w0);
        g_W0bh[idx] = w0h;
        g_W0bl[idx] = __float2bfloat16(w0 - __bfloat162float(w0h));
    }
}

// ---------------------------------------------------------------------------
// Grid barrier (all NCTAS co-resident: 136 <= 148 SMs).
// ---------------------------------------------------------------------------
__device__ __forceinline__ void grid_barrier(unsigned& phase) {
    __threadfence();
    __syncthreads();
    phase += NCTAS;
    if (threadIdx.x == 0) {
        atomicAdd(&g_bar, 1u);
        while (*(volatile unsigned*)&g_bar < phase) { }
        __threadfence();
    }
    __syncthreads();
}

// ---------------------------------------------------------------------------
// Persistent mma.sync rollout.
// Each CTA: one 128x128 tile of G5 = h @ W5^T as Ah*Bh + Ah*Bl + Al*Bh
// (bf16 operands, fp32 accum). 8 warps: wm = wid&3 (32 rows), wn = wid>>2
// (64 cols). K streamed in 32-element chunks, cp.async double-buffered.
// B tiles are n-major (k contiguous) -> loaded with NON-trans ldmatrix,
// which yields exactly the k-pair/.col fragment mma expects.
// ---------------------------------------------------------------------------
__global__ void __launch_bounds__(TPB, 1)
rollout(float* __restrict__ out, const float* __restrict__ b_head) {
    extern __shared__ __align__(128) char smem[];
    const uint32_t sm0 = smem_u32(smem);

    const int tid = threadIdx.x;
    const int lane = tid & 31;
    const int wid = tid >> 5;
    const int wm = wid & 3;        // 0..3 -> 32-row group
    const int wn = wid >> 2;       // 0..1 -> 64-col group
    const int cta = blockIdx.x;
    const int m0 = (cta & 3) * 128;
    const int n0 = (cta >> 2) * 128;
    const bool is_y = (n0 >= NG);

    // cp.async mapping: two passes of 256 threads per 512-segment buffer.
    const int lr = tid & 127;            // row within pass
    const int lc = (tid >> 7) & 1;       // half of the 4 segments

    // ldmatrix base offsets (bytes within a buffer).
    const uint32_t lm_row = (uint32_t)(lane & 15) * ROWB + (uint32_t)(lane >> 4) * 16;
    const uint32_t a_base = (uint32_t)(wm * 32) * ROWB + lm_row;
    const uint32_t b_base = (uint32_t)(wn * 64) * ROWB + lm_row;

    unsigned gphase = 0;

    const bf16* Amh = g_hbh + (size_t)m0 * KK;
    const bf16* Aml = g_hbl + (size_t)m0 * KK;

    for (int t = 0; t <= LL; ++t) {
        const bool active = (t < LL) ? !(t == 0 && is_y) : is_y;
        if (active) {
            const bf16* Bnh = ((t == 0) ? g_W0bh : g_Wbh) + (size_t)n0 * KK;
            const bf16* Bnl = ((t == 0) ? g_W0bl : g_Wbl) + (size_t)n0 * KK;

            float acc[2][8][4];
#pragma unroll
            for (int i = 0; i < 2; ++i)
#pragma unroll
                for (int j = 0; j < 8; ++j)
#pragma unroll
                    for (int k = 0; k < 4; ++k) acc[i][j][k] = 0.0f;

            // ---- chunk loader (buf: 0/1; kc0 = chunk*KC) ----
            auto load_chunk = [&](int chunk, int sbuf) {
                const uint32_t sb = sm0 + sbuf * STAGE_BYTES;
                const int kc0 = chunk * KC;
#pragma unroll
                for (int pass = 0; pass < 2; ++pass) {
                    const int seg = lr;                 // row 0..127
                    const int cs = lc + 2 * pass;       // 16B segment 0..3
                    const uint32_t soff = (uint32_t)seg * ROWB + (uint32_t)cs * 16;
                    const size_t goff = (size_t)seg * KK + kc0 + cs * 8;
                    CP_ASYNC16(sb + 0 * BUFB + soff, Amh + goff);
                    CP_ASYNC16(sb + 1 * BUFB + soff, Aml + goff);
                    CP_ASYNC16(sb + 2 * BUFB + soff, Bnh + goff);
                    CP_ASYNC16(sb + 3 * BUFB + soff, Bnl + goff);
                }
                CP_COMMIT();
            };

            load_chunk(0, 0);

            for (int c = 0; c < NCHUNK; ++c) {
                const int buf = c & 1;
                if (c + 1 < NCHUNK) {
                    load_chunk(c + 1, buf ^ 1);
                    cp_wait<1>();
                } else {
                    cp_wait<0>();
                }
                __syncthreads();

                const uint32_t sb = sm0 + buf * STAGE_BYTES;
#pragma unroll
                for (int ks = 0; ks < 2; ++ks) {
                    const uint32_t ko = (uint32_t)ks * 32;   // 16 halves
                    uint32_t ah[2][4], al[2][4];
#pragma unroll
                    for (int mt = 0; mt < 2; ++mt) {
                        ldsm_x4(ah[mt], sb + 0 * BUFB + a_base + (uint32_t)(mt * 16) * ROWB + ko);
                        ldsm_x4(al[mt], sb + 1 * BUFB + a_base + (uint32_t)(mt * 16) * ROWB + ko);
                    }
                    uint32_t bh[4][4], bl[4][4];
#pragma unroll
                    for (int nt = 0; nt < 4; ++nt) {
                        ldsm_x4(bh[nt], sb + 2 * BUFB + b_base + (uint32_t)(nt * 16) * ROWB + ko);
                        ldsm_x4(bl[nt], sb + 3 * BUFB + b_base + (uint32_t)(nt * 16) * ROWB + ko);
                    }
#pragma unroll
                    for (int mt = 0; mt < 2; ++mt)
#pragma unroll
                        for (int nt = 0; nt < 4; ++nt) {
                            mma_bf16(acc[mt][2 * nt + 0], ah[mt], bh[nt][0], bh[nt][2]);
                            mma_bf16(acc[mt][2 * nt + 1], ah[mt], bh[nt][1], bh[nt][3]);
                            mma_bf16(acc[mt][2 * nt + 0], ah[mt], bl[nt][0], bl[nt][2]);
                            mma_bf16(acc[mt][2 * nt + 1], ah[mt], bl[nt][1], bl[nt][3]);
                            mma_bf16(acc[mt][2 * nt + 0], al[mt], bh[nt][0], bh[nt][2]);
                            mma_bf16(acc[mt][2 * nt + 1], al[mt], bh[nt][1], bh[nt][3]);
                        }
                }
                __syncthreads();
            }

            // ---- epilogue ----
            const int r_base = m0 + wm * 32 + (lane >> 2);
            if (!is_y) {
#pragma unroll
                for (int mt = 0; mt < 2; ++mt) {
#pragma unroll
                    for (int n8 = 0; n8 < 8; ++n8) {
                        const int col = n0 + wn * 64 + n8 * 8 + (lane & 3) * 2;
                        const int row = r_base + mt * 16;
                        float2 v0 = make_float2(acc[mt][n8][0], acc[mt][n8][1]);
                        float2 v1 = make_float2(acc[mt][n8][2], acc[mt][n8][3]);
                        *reinterpret_cast<float2*>(g_G + (size_t)row * NG + col) = v0;
                        *reinterpret_cast<float2*>(g_G + (size_t)(row + 8) * NG + col) = v1;
                    }
                }
            } else {
                float* yb = out + (size_t)(t - 1) * BB * II;
#pragma unroll
                for (int mt = 0; mt < 2; ++mt) {
#pragma unroll
                    for (int n8 = 0; n8 < 8; ++n8) {
                        const int col = (n0 - NG) + wn * 64 + n8 * 8 + (lane & 3) * 2;
                        const int row = r_base + mt * 16;
                        const float bh0 = __ldg(b_head + col);
                        const float bh1 = __ldg(b_head + col + 1);
                        float2 v0 = make_float2(acc[mt][n8][0] + bh0, acc[mt][n8][1] + bh1);
                        float2 v1 = make_float2(acc[mt][n8][2] + bh0, acc[mt][n8][3] + bh1);
                        *reinterpret_cast<float2*>(yb + (size_t)row * II + col) = v0;
                        *reinterpret_cast<float2*>(yb + (size_t)(row + 8) * II + col) = v1;
                    }
                }
            }
        }

        if (t == LL) break;

        grid_barrier(gphase);

        {   // GRU gates + bf16 split of the new hidden state.
            const float* bias = (t == 0) ? g_b50 : g_b5;
            for (int i = cta * TPB + tid; i < BB * HH; i += NCTAS * TPB) {
                int b = i >> 10, j = i & 1023;
                const float* Gr = g_G + (size_t)b * NG;
                float rp  = Gr[j]        + __ldg(bias + j);
                float zp  = Gr[1024 + j] + __ldg(bias + 1024 + j);
                float gin = Gr[2048 + j] + __ldg(bias + 2048 + j);
                float ghn = Gr[3072 + j] + __ldg(bias + 3072 + j);
                float r = 1.0f / (1.0f + expf(-rp));
                float z = 1.0f / (1.0f + expf(-zp));
                float nn = tanhf(gin + r * ghn);
                float hnew = (1.0f - z) * nn + z * g_h[i];
                g_h[i] = hnew;
                bf16 h0 = __float2bfloat16(hnew);
                g_hbh[i] = h0;
                g_hbl[i] = __float2bfloat16(hnew - __bfloat162float(h0));
            }
        }

        grid_barrier(gphase);
    }
}

// ---------------------------------------------------------------------------
// 6 graph nodes: init, bias, assemble, wc_gemm, split, rollout.
// ---------------------------------------------------------------------------
extern "C" void kernel_launch(void* const* d_in, const int* in_sizes, int n_in,
                              void* d_out, int out_size) {
    const float *ctx = nullptr, *Wih = nullptr, *Whh = nullptr,
                *bih = nullptr, *bhh = nullptr, *Whead = nullptr, *bhead = nullptr;
    int b3_seen = 0;
    for (int i = 0; i < n_in; i++) {
        long sz = in_sizes[i];
        const float* p = (const float*)d_in[i];
        if (sz == (long)BB * HH) ctx = p;
        else if (sz == (long)G3 * II) Wih = p;
        else if (sz == (long)G3 * HH) Whh = p;
        else if (sz == (long)G3) { if (b3_seen++ == 0) bih = p; else bhh = p; }
        else if (sz == (long)II * HH) Whead = p;
        else if (sz == (long)II) bhead = p;
    }
    float* out = (float*)d_out;

    cudaFuncSetAttribute(rollout, cudaFuncAttributeMaxDynamicSharedMemorySize, SMEM_DYN);

    init_state<<<(BB * HH + 255) / 256, 256>>>(ctx);
    build_bias<<<NG / 256, 256>>>(Wih, bih, bhh, bhead);
    assemble_w<<<512, 256>>>(Whh, Whead);
    wc_gemm<<<dim3(KK / 64, G3 / 64), 256>>>(Wih, Whh, Whead);
    split_w<<<1024, 256>>>();
    rollout<<<NCTAS, TPB, SMEM_DYN>>>(out, bhead);

    (void)out_size;
    (void)n_in;
}

// round 6
// speedup vs baseline: 3.6334x; 2.4208x over previous
#include <cuda_runtime.h>
#include <cuda_fp16.h>
#include <cstdint>

// Shapes fixed by the reference.
#define BB 512     // batch
#define HH 1024    // hidden
#define II 256     // input / output feature
#define LL 256     // rollout length
#define G3 3072    // 3*HH
#define NG 4096    // gate GEMM output width (4*HH)
#define N5 4352    // NG + II (appended W_head rows -> y)
#define KK 1024    // GEMM K
#define NCTAS 136  // 4 m-tiles x 34 n-tiles (128x128)
#define TPB 256

#define KC 64                    // fp16 K elements per chunk (128 bytes/row)
#define NCHUNK (KK / KC)         // 16
#define ROWB 144                 // padded smem row bytes (128 + 16)
#define BUFB (128 * ROWB)        // 18432 B per 128x64 fp16 tile
#define STAGE_BYTES (3 * BUFB)   // Ah, Al, W
#define SMEM_DYN (2 * STAGE_BYTES)

typedef __half fp16;

// ---------------------------------------------------------------------------
// Static device scratch.
// ---------------------------------------------------------------------------
__device__ fp16  g_hbh[BB * HH];        // fp16 hi part of h
__device__ fp16  g_hbl[BB * HH];        // fp16 lo part of h
__device__ float g_W5[N5 * KK];         // folded weights (fp32, old layout)
__device__ float g_W50[N5 * KK];        // step-0 folded weights (old layout)
__device__ fp16  g_Wf[N5 * KK];         // fp16 weights, gate-interleaved layout
__device__ fp16  g_W0f[N5 * KK];        // fp16 step-0 weights, interleaved
__device__ float g_b5[NG];              // biases (old gate-major layout)
__device__ float g_b50[NG];
__device__ unsigned g_bar;

// ---------------------------------------------------------------------------
// PTX helpers (base ISA, valid on compute_103)
// ---------------------------------------------------------------------------
__device__ __forceinline__ uint32_t smem_u32(const void* p) {
    uint32_t a;
    asm("{ .reg .u64 t; cvta.to.shared.u64 t, %1; cvt.u32.u64 %0, t; }" : "=r"(a) : "l"(p));
    return a;
}
__device__ __forceinline__ void ldsm_x4(uint32_t* r, uint32_t addr) {
    asm volatile("ldmatrix.sync.aligned.m8n8.x4.shared.b16 {%0,%1,%2,%3}, [%4];"
                 : "=r"(r[0]), "=r"(r[1]), "=r"(r[2]), "=r"(r[3]) : "r"(addr));
}
__device__ __forceinline__ void mma_fp16(float* d, const uint32_t* a,
                                         uint32_t b0, uint32_t b1) {
    asm volatile(
        "mma.sync.aligned.m16n8k16.row.col.f32.f16.f16.f32 "
        "{%0,%1,%2,%3}, {%4,%5,%6,%7}, {%8,%9}, {%0,%1,%2,%3};"
        : "+f"(d[0]), "+f"(d[1]), "+f"(d[2]), "+f"(d[3])
        : "r"(a[0]), "r"(a[1]), "r"(a[2]), "r"(a[3]), "r"(b0), "r"(b1));
}
#define CP_ASYNC16(smem, gptr) \
    asm volatile("cp.async.cg.shared.global [%0], [%1], 16;" :: "r"(smem), "l"(gptr))
#define CP_COMMIT() asm volatile("cp.async.commit_group;" ::: "memory")
template <int N>
__device__ __forceinline__ void cp_wait() {
    asm volatile("cp.async.wait_group %0;" :: "n"(N) : "memory");
}

// ---------------------------------------------------------------------------
// Setup kernels
// ---------------------------------------------------------------------------
__global__ void init_state(const float* __restrict__ ctx) {
    int i = blockIdx.x * blockDim.x + threadIdx.x;
    if (i < BB * HH) {
        float v = ctx[i];
        fp16 h0 = __float2half(v);
        g_hbh[i] = h0;
        g_hbl[i] = __float2half(v - __half2float(h0));
    }
    if (i == 0) g_bar = 0u;
}

__global__ void build_bias(const float* __restrict__ Wih,
                           const float* __restrict__ bih,
                           const float* __restrict__ bhh,
                           const float* __restrict__ bhead) {
    int j = blockIdx.x * blockDim.x + threadIdx.x;
    if (j >= NG) return;
    float v0, v1;
    if (j < 2048)      v0 = bih[j] + bhh[j];
    else if (j < G3)   v0 = bih[j];
    else               v0 = bhh[j - 1024];
    if (j < G3) {
        float d = 0.0f;
        const float* wr = Wih + (size_t)j * II;
        for (int i = 0; i < II; ++i) d += wr[i] * bhead[i];
        float bc = bih[j] + d;
        v1 = (j < 2048) ? (bhh[j] + bc) : bc;
    } else {
        v1 = bhh[j - 1024];
    }
    g_b50[j] = v0;
    g_b5[j]  = v1;
}

__global__ void assemble_w(const float* __restrict__ Whh,
                           const float* __restrict__ Whead) {
    for (int idx = blockIdx.x * blockDim.x + threadIdx.x;
         idx < N5 * KK; idx += gridDim.x * blockDim.x) {
        int n = idx >> 10;
        float v;
        if (n < 2048)      v = Whh[idx];
        else if (n < G3)   v = 0.0f;
        else if (n < NG)   v = Whh[idx - 1024 * KK];
        else               v = Whead[idx - NG * KK];
        g_W50[idx] = v;
        if (n >= G3) g_W5[idx] = v;
    }
}

__global__ void __launch_bounds__(256)
wc_gemm(const float* __restrict__ Wih,
        const float* __restrict__ Whh,
        const float* __restrict__ Whead) {
    __shared__ __align__(16) float As[16][68];
    __shared__ __align__(16) float Bs[16][68];
    const int tid = threadIdx.x;
    const int n0 = blockIdx.y * 64;
    const int k0 = blockIdx.x * 64;
    const int ty = tid >> 4, tx = tid & 15;

    float acc[4][4] = {};
    for (int i0 = 0; i0 < II; i0 += 16) {
        {
            int row = tid >> 2, ic = (tid & 3) * 4;
            float4 av = *reinterpret_cast<const float4*>(Wih + (size_t)(n0 + row) * II + i0 + ic);
            As[ic + 0][row] = av.x; As[ic + 1][row] = av.y;
            As[ic + 2][row] = av.z; As[ic + 3][row] = av.w;
        }
        {
            int r = tid >> 4, kc = (tid & 15) * 4;
            float4 bv = *reinterpret_cast<const float4*>(Whead + (size_t)(i0 + r) * KK + k0 + kc);
            *reinterpret_cast<float4*>(&Bs[r][kc]) = bv;
        }
        __syncthreads();
#pragma unroll
        for (int i = 0; i < 16; ++i) {
            float a[4], b[4];
#pragma unroll
            for (int u = 0; u < 4; ++u) a[u] = As[i][ty * 4 + u];
#pragma unroll
            for (int u = 0; u < 4; ++u) b[u] = Bs[i][tx * 4 + u];
#pragma unroll
            for (int r = 0; r < 4; ++r)
#pragma unroll
                for (int c = 0; c < 4; ++c) acc[r][c] = fmaf(a[r], b[c], acc[r][c]);
        }
        __syncthreads();
    }
#pragma unroll
    for (int r = 0; r < 4; ++r) {
        int n = n0 + ty * 4 + r;
#pragma unroll
        for (int c = 0; c < 4; ++c) {
            int k = k0 + tx * 4 + c;
            float w = acc[r][c];
            if (n < 2048) w += Whh[(size_t)n * KK + k];
            g_W5[(size_t)n * KK + k] = w;
        }
    }
}

// Permute gate rows into interleaved layout + convert to fp16.
// old row o = g*1024 + j (g<4)  ->  new row = (j/32)*128 + g*32 + (j%32)
// y rows (o >= 4096) stay in place.
__global__ void split_w() {
    for (int idx = blockIdx.x * blockDim.x + threadIdx.x;
         idx < N5 * KK; idx += gridDim.x * blockDim.x) {
        int o = idx >> 10;
        int k = idx & 1023;
        int nrow;
        if (o < NG) {
            int g = o >> 10;
            int j = o & 1023;
            nrow = (j >> 5) * 128 + g * 32 + (j & 31);
        } else {
            nrow = o;
        }
        size_t dst = (size_t)nrow * KK + k;
        g_Wf[dst]  = __float2half(g_W5[idx]);
        g_W0f[dst] = __float2half(g_W50[idx]);
    }
}

// ---------------------------------------------------------------------------
// Grid barrier (all NCTAS co-resident: 136 <= 148 SMs).
// ---------------------------------------------------------------------------
__device__ __forceinline__ void grid_barrier(unsigned& phase) {
    __threadfence();
    __syncthreads();
    phase += NCTAS;
    if (threadIdx.x == 0) {
        atomicAdd(&g_bar, 1u);
        while (*(volatile unsigned*)&g_bar < phase) { }
        __threadfence();
    }
    __syncthreads();
}

// ---------------------------------------------------------------------------
// Persistent rollout with fused gates.
//  - CTA (m, nt): 128x128 tile of G = h @ Wf^T, h = Ah + Al (fp16 split).
//  - nt < 32: tile cols = [r|z|gn|ghn] x 32 j's (j = 32*nt + jj) -> gates
//    computed in-register in the epilogue; h_old lives in registers.
//  - nt >= 32: y tile -> written straight to out.
//  - ONE grid barrier per step.
// ---------------------------------------------------------------------------
__global__ void __launch_bounds__(TPB, 1)
rollout(float* __restrict__ out, const float* __restrict__ ctx,
        const float* __restrict__ b_head) {
    extern __shared__ __align__(128) char smem[];
    __shared__ float s_b5[128], s_b50[128];
    const uint32_t sm0 = smem_u32(smem);

    const int tid = threadIdx.x;
    const int lane = tid & 31;
    const int wid = tid >> 5;            // warp 0..7 -> rows 16*wid .. +15
    const int cta = blockIdx.x;
    const int m0 = (cta & 3) * 128;
    const int nt = cta >> 2;             // 0..33
    const bool is_y = (nt >= 32);

    // Per-CTA bias staging.
    if (!is_y) {
        if (tid < 128) {
            int g = tid >> 5, jj = tid & 31;
            s_b5[tid]  = g_b5[g * 1024 + 32 * nt + jj];
            s_b50[tid] = g_b50[g * 1024 + 32 * nt + jj];
        }
    } else {
        if (tid < 128) s_b5[tid] = __ldg(b_head + (nt - 32) * 128 + tid);
    }
    __syncthreads();

    // Register-resident h_old (gate CTAs): rows r0, r0+8; jj = 8q+2(lane&3)+e.
    const int r0 = m0 + 16 * wid + (lane >> 2);
    const int jc = 2 * (lane & 3);
    float ho[16];
    if (!is_y) {
#pragma unroll
        for (int rs = 0; rs < 2; ++rs)
#pragma unroll
            for (int q = 0; q < 4; ++q)
#pragma unroll
                for (int e = 0; e < 2; ++e)
                    ho[rs * 8 + q * 2 + e] =
                        ctx[(size_t)(r0 + 8 * rs) * HH + 32 * nt + 8 * q + jc + e];
    }

    // cp.async mapping: 1024 16B segments per tile, 4 per thread.
    // ldmatrix lane offset.
    const uint32_t lm = (uint32_t)(lane & 15) * ROWB + (uint32_t)(lane >> 4) * 16;

    const fp16* Amh = g_hbh + (size_t)m0 * KK;
    const fp16* Aml = g_hbl + (size_t)m0 * KK;

    unsigned gphase = 0;

    for (int t = 0; t <= LL; ++t) {
        const bool active = (t < LL) ? !(t == 0 && is_y) : is_y;
        if (active) {
            const fp16* Bw = ((t == 0) ? g_W0f : g_Wf) + (size_t)(nt * 128) * KK;

            float acc[16][4];
#pragma unroll
            for (int i = 0; i < 16; ++i)
#pragma unroll
                for (int k = 0; k < 4; ++k) acc[i][k] = 0.0f;

            auto load_chunk = [&](int chunk, int sbuf) {
                const uint32_t sb = sm0 + sbuf * STAGE_BYTES;
                const int kc0 = chunk * KC;
#pragma unroll
                for (int p = 0; p < 4; ++p) {
                    const int s = tid + 256 * p;
                    const int row = s >> 3;
                    const int cs = s & 7;
                    const uint32_t soff = (uint32_t)row * ROWB + (uint32_t)cs * 16;
                    const size_t goff = (size_t)row * KK + kc0 + cs * 8;
                    CP_ASYNC16(sb + 0 * BUFB + soff, Amh + goff);
                    CP_ASYNC16(sb + 1 * BUFB + soff, Aml + goff);
                    CP_ASYNC16(sb + 2 * BUFB + soff, Bw + goff);
                }
                CP_COMMIT();
            };

            load_chunk(0, 0);

            for (int c = 0; c < NCHUNK; ++c) {
                const int buf = c & 1;
                if (c + 1 < NCHUNK) {
                    load_chunk(c + 1, buf ^ 1);
                    cp_wait<1>();
                } else {
                    cp_wait<0>();
                }
                __syncthreads();

                const uint32_t sb = sm0 + buf * STAGE_BYTES;
                const uint32_t abase = sb + (uint32_t)(16 * wid) * ROWB + lm;
#pragma unroll
                for (int ks = 0; ks < 4; ++ks) {
                    const uint32_t ko = (uint32_t)ks * 32;
                    uint32_t ah[4], al[4];
                    ldsm_x4(ah, abase + ko);
                    ldsm_x4(al, abase + BUFB + ko);
#pragma unroll
                    for (int u = 0; u < 8; ++u) {
                        uint32_t bb[4];
                        ldsm_x4(bb, sb + 2 * BUFB + (uint32_t)(16 * u) * ROWB + lm + ko);
                        mma_fp16(acc[2 * u + 0], ah, bb[0], bb[2]);
                        mma_fp16(acc[2 * u + 1], ah, bb[1], bb[3]);
                        mma_fp16(acc[2 * u + 0], al, bb[0], bb[2]);
                        mma_fp16(acc[2 * u + 1], al, bb[1], bb[3]);
                    }
                }
                __syncthreads();
            }

            // ---- fused epilogue ----
            if (!is_y) {
                const float* sb = (t == 0) ? s_b50 : s_b5;
#pragma unroll
                for (int rs = 0; rs < 2; ++rs) {
                    const int row = r0 + 8 * rs;
#pragma unroll
                    for (int q = 0; q < 4; ++q) {
                        float hn[2];
#pragma unroll
                        for (int e = 0; e < 2; ++e) {
                            const int cb = 8 * q + jc + e;
                            float rp = acc[q][2 * rs + e]      + sb[cb];
                            float zp = acc[4 + q][2 * rs + e]  + sb[32 + cb];
                            float gn = acc[8 + q][2 * rs + e]  + sb[64 + cb];
                            float gh = acc[12 + q][2 * rs + e] + sb[96 + cb];
                            float r = 1.0f / (1.0f + expf(-rp));
                            float z = 1.0f / (1.0f + expf(-zp));
                            float nn = tanhf(gn + r * gh);
                            float hnew = (1.0f - z) * nn + z * ho[rs * 8 + q * 2 + e];
                            ho[rs * 8 + q * 2 + e] = hnew;
                            hn[e] = hnew;
                        }
                        // fp16 split + packed write.
                        const int jb = 32 * nt + 8 * q + jc;
                        __half2 vh = __floats2half2_rn(hn[0], hn[1]);
                        float l0 = hn[0] - __half2float(__low2half(vh));
                        float l1 = hn[1] - __half2float(__high2half(vh));
                        __half2 vl = __floats2half2_rn(l0, l1);
                        *reinterpret_cast<__half2*>(g_hbh + (size_t)row * HH + jb) = vh;
                        *reinterpret_cast<__half2*>(g_hbl + (size_t)row * HH + jb) = vl;
                    }
                }
            } else {
                float* yb = out + (size_t)(t - 1) * BB * II;
#pragma unroll
                for (int rs = 0; rs < 2; ++rs) {
                    const int row = r0 + 8 * rs;
#pragma unroll
                    for (int f = 0; f < 16; ++f) {
                        const int ci = 8 * f + jc;                 // col in tile
                        const int col = (nt - 32) * 128 + ci;
                        float2 v = make_float2(acc[f][2 * rs + 0] + s_b5[ci],
                                               acc[f][2 * rs + 1] + s_b5[ci + 1]);
                        *reinterpret_cast<float2*>(yb + (size_t)row * II + col) = v;
                    }
                }
            }
        }

        if (t == LL) break;
        grid_barrier(gphase);
    }
}

// ---------------------------------------------------------------------------
// 6 graph nodes: init, bias, assemble, wc_gemm, split, rollout.
// ---------------------------------------------------------------------------
extern "C" void kernel_launch(void* const* d_in, const int* in_sizes, int n_in,
                              void* d_out, int out_size) {
    const float *ctx = nullptr, *Wih = nullptr, *Whh = nullptr,
                *bih = nullptr, *bhh = nullptr, *Whead = nullptr, *bhead = nullptr;
    int b3_seen = 0;
    for (int i = 0; i < n_in; i++) {
        long sz = in_sizes[i];
        const float* p = (const float*)d_in[i];
        if (sz == (long)BB * HH) ctx = p;
        else if (sz == (long)G3 * II) Wih = p;
        else if (sz == (long)G3 * HH) Whh = p;
        else if (sz == (long)G3) { if (b3_seen++ == 0) bih = p; else bhh = p; }
        else if (sz == (long)II * HH) Whead = p;
        else if (sz == (long)II) bhead = p;
    }
    float* out = (float*)d_out;

    cudaFuncSetAttribute(rollout, cudaFuncAttributeMaxDynamicSharedMemorySize, SMEM_DYN);

    init_state<<<(BB * HH + 255) / 256, 256>>>(ctx);
    build_bias<<<NG / 256, 256>>>(Wih, bih, bhh, bhead);
    assemble_w<<<512, 256>>>(Whh, Whead);
    wc_gemm<<<dim3(KK / 64, G3 / 64), 256>>>(Wih, Whh, Whead);
    split_w<<<1024, 256>>>();
    rollout<<<NCTAS, TPB, SMEM_DYN>>>(out, ctx, bhead);

    (void)out_size;
    (void)n_in;
}

// round 7
// speedup vs baseline: 5.6376x; 1.5516x over previous
#include <cuda_runtime.h>
#include <cuda_fp16.h>
#include <cstdint>

// Shapes fixed by the reference.
#define BB 512     // batch
#define HH 1024    // hidden
#define II 256     // input / output feature
#define LL 256     // rollout length
#define G3 3072    // 3*HH
#define NG 4096    // gate GEMM output width (4*HH)
#define N5 4352    // NG + II (appended W_head rows -> y)
#define KK 1024    // GEMM K
#define NCTAS 136  // 4 m-tiles x 34 n-tiles (128x128)
#define TPB 256

#define KC 64                    // fp16 K elements per chunk (128 bytes/row)
#define NCHUNK (KK / KC)         // 16
#define ROWB 144                 // padded smem row bytes (128 + 16)
#define BUFB (128 * ROWB)        // 18432 B per 128x64 fp16 tile
#define STAGE_BYTES (2 * BUFB)   // A, W
#define NSTG 3
#define SMEM_DYN (NSTG * STAGE_BYTES)

typedef __half fp16;

// ---------------------------------------------------------------------------
// Static device scratch.
// ---------------------------------------------------------------------------
__device__ fp16  g_hb[BB * HH];         // fp16 hidden state (GEMM input)
__device__ float g_W5[N5 * KK];         // folded weights (fp32, old layout)
__device__ float g_W50[N5 * KK];        // step-0 folded weights (old layout)
__device__ fp16  g_Wf[N5 * KK];         // fp16 weights, gate-interleaved layout
__device__ fp16  g_W0f[N5 * KK];        // fp16 step-0 weights, interleaved
__device__ float g_b5[NG];              // biases (gate-major layout)
__device__ float g_b50[NG];
__device__ unsigned g_bar;

// ---------------------------------------------------------------------------
// PTX helpers (base ISA, valid on compute_103)
// ---------------------------------------------------------------------------
__device__ __forceinline__ uint32_t smem_u32(const void* p) {
    uint32_t a;
    asm("{ .reg .u64 t; cvta.to.shared.u64 t, %1; cvt.u32.u64 %0, t; }" : "=r"(a) : "l"(p));
    return a;
}
__device__ __forceinline__ void ldsm_x4(uint32_t* r, uint32_t addr) {
    asm volatile("ldmatrix.sync.aligned.m8n8.x4.shared.b16 {%0,%1,%2,%3}, [%4];"
                 : "=r"(r[0]), "=r"(r[1]), "=r"(r[2]), "=r"(r[3]) : "r"(addr));
}
__device__ __forceinline__ void mma_fp16(float* d, const uint32_t* a,
                                         uint32_t b0, uint32_t b1) {
    asm volatile(
        "mma.sync.aligned.m16n8k16.row.col.f32.f16.f16.f32 "
        "{%0,%1,%2,%3}, {%4,%5,%6,%7}, {%8,%9}, {%0,%1,%2,%3};"
        : "+f"(d[0]), "+f"(d[1]), "+f"(d[2]), "+f"(d[3])
        : "r"(a[0]), "r"(a[1]), "r"(a[2]), "r"(a[3]), "r"(b0), "r"(b1));
}
#define CP_ASYNC16(smem, gptr) \
    asm volatile("cp.async.cg.shared.global [%0], [%1], 16;" :: "r"(smem), "l"(gptr))
#define CP_COMMIT() asm volatile("cp.async.commit_group;" ::: "memory")
template <int N>
__device__ __forceinline__ void cp_wait() {
    asm volatile("cp.async.wait_group %0;" :: "n"(N) : "memory");
}

// ---------------------------------------------------------------------------
// Setup kernels
// ---------------------------------------------------------------------------
__global__ void init_state(const float* __restrict__ ctx) {
    int i = blockIdx.x * blockDim.x + threadIdx.x;
    if (i < BB * HH) g_hb[i] = __float2half(ctx[i]);
    if (i == 0) g_bar = 0u;
}

__global__ void build_bias(const float* __restrict__ Wih,
                           const float* __restrict__ bih,
                           const float* __restrict__ bhh,
                           const float* __restrict__ bhead) {
    int j = blockIdx.x * blockDim.x + threadIdx.x;
    if (j >= NG) return;
    float v0, v1;
    if (j < 2048)      v0 = bih[j] + bhh[j];
    else if (j < G3)   v0 = bih[j];
    else               v0 = bhh[j - 1024];
    if (j < G3) {
        float d = 0.0f;
        const float* wr = Wih + (size_t)j * II;
        for (int i = 0; i < II; ++i) d += wr[i] * bhead[i];
        float bc = bih[j] + d;
        v1 = (j < 2048) ? (bhh[j] + bc) : bc;
    } else {
        v1 = bhh[j - 1024];
    }
    g_b50[j] = v0;
    g_b5[j]  = v1;
}

__global__ void assemble_w(const float* __restrict__ Whh,
                           const float* __restrict__ Whead) {
    for (int idx = blockIdx.x * blockDim.x + threadIdx.x;
         idx < N5 * KK; idx += gridDim.x * blockDim.x) {
        int n = idx >> 10;
        float v;
        if (n < 2048)      v = Whh[idx];
        else if (n < G3)   v = 0.0f;
        else if (n < NG)   v = Whh[idx - 1024 * KK];
        else               v = Whead[idx - NG * KK];
        g_W50[idx] = v;
        if (n >= G3) g_W5[idx] = v;
    }
}

__global__ void __launch_bounds__(256)
wc_gemm(const float* __restrict__ Wih,
        const float* __restrict__ Whh,
        const float* __restrict__ Whead) {
    __shared__ __align__(16) float As[16][68];
    __shared__ __align__(16) float Bs[16][68];
    const int tid = threadIdx.x;
    const int n0 = blockIdx.y * 64;
    const int k0 = blockIdx.x * 64;
    const int ty = tid >> 4, tx = tid & 15;

    float acc[4][4] = {};
    for (int i0 = 0; i0 < II; i0 += 16) {
        {
            int row = tid >> 2, ic = (tid & 3) * 4;
            float4 av = *reinterpret_cast<const float4*>(Wih + (size_t)(n0 + row) * II + i0 + ic);
            As[ic + 0][row] = av.x; As[ic + 1][row] = av.y;
            As[ic + 2][row] = av.z; As[ic + 3][row] = av.w;
        }
        {
            int r = tid >> 4, kc = (tid & 15) * 4;
            float4 bv = *reinterpret_cast<const float4*>(Whead + (size_t)(i0 + r) * KK + k0 + kc);
            *reinterpret_cast<float4*>(&Bs[r][kc]) = bv;
        }
        __syncthreads();
#pragma unroll
        for (int i = 0; i < 16; ++i) {
            float a[4], b[4];
#pragma unroll
            for (int u = 0; u < 4; ++u) a[u] = As[i][ty * 4 + u];
#pragma unroll
            for (int u = 0; u < 4; ++u) b[u] = Bs[i][tx * 4 + u];
#pragma unroll
            for (int r = 0; r < 4; ++r)
#pragma unroll
                for (int c = 0; c < 4; ++c) acc[r][c] = fmaf(a[r], b[c], acc[r][c]);
        }
        __syncthreads();
    }
#pragma unroll
    for (int r = 0; r < 4; ++r) {
        int n = n0 + ty * 4 + r;
#pragma unroll
        for (int c = 0; c < 4; ++c) {
            int k = k0 + tx * 4 + c;
            float w = acc[r][c];
            if (n < 2048) w += Whh[(size_t)n * KK + k];
            g_W5[(size_t)n * KK + k] = w;
        }
    }
}

// Permute gate rows into interleaved layout + convert to fp16.
// old row o = g*1024 + j (g<4)  ->  new row = (j/32)*128 + g*32 + (j%32)
__global__ void split_w() {
    for (int idx = blockIdx.x * blockDim.x + threadIdx.x;
         idx < N5 * KK; idx += gridDim.x * blockDim.x) {
        int o = idx >> 10;
        int k = idx & 1023;
        int nrow;
        if (o < NG) {
            int g = o >> 10;
            int j = o & 1023;
            nrow = (j >> 5) * 128 + g * 32 + (j & 31);
        } else {
            nrow = o;
        }
        size_t dst = (size_t)nrow * KK + k;
        g_Wf[dst]  = __float2half(g_W5[idx]);
        g_W0f[dst] = __float2half(g_W50[idx]);
    }
}

// ---------------------------------------------------------------------------
// Grid barrier (all NCTAS co-resident: 136 <= 148 SMs).
// ---------------------------------------------------------------------------
__device__ __forceinline__ void grid_barrier(unsigned& phase) {
    __threadfence();
    __syncthreads();
    phase += NCTAS;
    if (threadIdx.x == 0) {
        atomicAdd(&g_bar, 1u);
        while (*(volatile unsigned*)&g_bar < phase) { }
        __threadfence();
    }
    __syncthreads();
}

// ---------------------------------------------------------------------------
// Persistent rollout, fused gates, single fp16 h, 3-stage cp.async pipeline.
// ---------------------------------------------------------------------------
__global__ void __launch_bounds__(TPB, 1)
rollout(float* __restrict__ out, const float* __restrict__ ctx,
        const float* __restrict__ b_head) {
    extern __shared__ __align__(128) char smem[];
    __shared__ float s_b5[128], s_b50[128];
    const uint32_t sm0 = smem_u32(smem);

    const int tid = threadIdx.x;
    const int lane = tid & 31;
    const int wid = tid >> 5;            // warp 0..7 -> rows 16*wid .. +15
    const int cta = blockIdx.x;
    const int m0 = (cta & 3) * 128;
    const int nt = cta >> 2;             // 0..33
    const bool is_y = (nt >= 32);

    // Per-CTA bias staging.
    if (!is_y) {
        if (tid < 128) {
            int g = tid >> 5, jj = tid & 31;
            s_b5[tid]  = g_b5[g * 1024 + 32 * nt + jj];
            s_b50[tid] = g_b50[g * 1024 + 32 * nt + jj];
        }
    } else {
        if (tid < 128) s_b5[tid] = __ldg(b_head + (nt - 32) * 128 + tid);
    }
    __syncthreads();

    // Register-resident fp32 h_old (gate CTAs).
    const int r0 = m0 + 16 * wid + (lane >> 2);
    const int jc = 2 * (lane & 3);
    float ho[16];
    if (!is_y) {
#pragma unroll
        for (int rs = 0; rs < 2; ++rs)
#pragma unroll
            for (int q = 0; q < 4; ++q)
#pragma unroll
                for (int e = 0; e < 2; ++e)
                    ho[rs * 8 + q * 2 + e] =
                        ctx[(size_t)(r0 + 8 * rs) * HH + 32 * nt + 8 * q + jc + e];
    }

    const uint32_t lm = (uint32_t)(lane & 15) * ROWB + (uint32_t)(lane >> 4) * 16;
    const fp16* Am = g_hb + (size_t)m0 * KK;

    unsigned gphase = 0;

    for (int t = 0; t <= LL; ++t) {
        const bool active = (t < LL) ? !(t == 0 && is_y) : is_y;
        if (active) {
            const fp16* Bw = ((t == 0) ? g_W0f : g_Wf) + (size_t)(nt * 128) * KK;

            float acc[16][4];
#pragma unroll
            for (int i = 0; i < 16; ++i)
#pragma unroll
                for (int k = 0; k < 4; ++k) acc[i][k] = 0.0f;

            auto load_chunk = [&](int chunk, int sbuf) {
                const uint32_t sb = sm0 + sbuf * STAGE_BYTES;
                const int kc0 = chunk * KC;
#pragma unroll
                for (int p = 0; p < 4; ++p) {
                    const int s = tid + 256 * p;
                    const int row = s >> 3;
                    const int cs = s & 7;
                    const uint32_t soff = (uint32_t)row * ROWB + (uint32_t)cs * 16;
                    const size_t goff = (size_t)row * KK + kc0 + cs * 8;
                    CP_ASYNC16(sb + 0 * BUFB + soff, Am + goff);
                    CP_ASYNC16(sb + 1 * BUFB + soff, Bw + goff);
                }
                CP_COMMIT();
            };

            load_chunk(0, 0);
            load_chunk(1, 1);

            int sbuf = 0;                       // stage of chunk c
            for (int c = 0; c < NCHUNK; ++c) {
                if (c + 1 < NCHUNK) cp_wait<1>(); else cp_wait<0>();
                __syncthreads();
                // Load 2 chunks ahead into the stage freed by chunk c-1.
                // Safe: all warps finished chunk c-1 before the sync above.
                if (c + 2 < NCHUNK) {
                    int ns = sbuf + 2; if (ns >= NSTG) ns -= NSTG;
                    load_chunk(c + 2, ns);
                }

                const uint32_t sb = sm0 + sbuf * STAGE_BYTES;
                const uint32_t abase = sb + (uint32_t)(16 * wid) * ROWB + lm;
#pragma unroll
                for (int ks = 0; ks < 4; ++ks) {
                    const uint32_t ko = (uint32_t)ks * 32;
                    uint32_t ah[4];
                    ldsm_x4(ah, abase + ko);
#pragma unroll
                    for (int u = 0; u < 8; ++u) {
                        uint32_t bb[4];
                        ldsm_x4(bb, sb + BUFB + (uint32_t)(16 * u) * ROWB + lm + ko);
                        mma_fp16(acc[2 * u + 0], ah, bb[0], bb[2]);
                        mma_fp16(acc[2 * u + 1], ah, bb[1], bb[3]);
                    }
                }
                if (++sbuf == NSTG) sbuf = 0;
            }

            // ---- fused epilogue ----
            if (!is_y) {
                const float* sb = (t == 0) ? s_b50 : s_b5;
#pragma unroll
                for (int rs = 0; rs < 2; ++rs) {
                    const int row = r0 + 8 * rs;
#pragma unroll
                    for (int q = 0; q < 4; ++q) {
                        float hn[2];
#pragma unroll
                        for (int e = 0; e < 2; ++e) {
                            const int cb = 8 * q + jc + e;
                            float rp = acc[q][2 * rs + e]      + sb[cb];
                            float zp = acc[4 + q][2 * rs + e]  + sb[32 + cb];
                            float gn = acc[8 + q][2 * rs + e]  + sb[64 + cb];
                            float gh = acc[12 + q][2 * rs + e] + sb[96 + cb];
                            float r = 1.0f / (1.0f + expf(-rp));
                            float z = 1.0f / (1.0f + expf(-zp));
                            float nn = tanhf(gn + r * gh);
                            float hnew = (1.0f - z) * nn + z * ho[rs * 8 + q * 2 + e];
                            ho[rs * 8 + q * 2 + e] = hnew;
                            hn[e] = hnew;
                        }
                        const int jb = 32 * nt + 8 * q + jc;
                        __half2 vh = __floats2half2_rn(hn[0], hn[1]);
                        *reinterpret_cast<__half2*>(g_hb + (size_t)row * HH + jb) = vh;
                    }
                }
            } else {
                float* yb = out + (size_t)(t - 1) * BB * II;
#pragma unroll
                for (int rs = 0; rs < 2; ++rs) {
                    const int row = r0 + 8 * rs;
#pragma unroll
                    for (int f = 0; f < 16; ++f) {
                        const int ci = 8 * f + jc;                 // col in tile
                        const int col = (nt - 32) * 128 + ci;
                        float2 v = make_float2(acc[f][2 * rs + 0] + s_b5[ci],
                                               acc[f][2 * rs + 1] + s_b5[ci + 1]);
                        *reinterpret_cast<float2*>(yb + (size_t)row * II + col) = v;
                    }
                }
            }
        }

        if (t == LL) break;
        grid_barrier(gphase);
    }
}

// ---------------------------------------------------------------------------
// 6 graph nodes: init, bias, assemble, wc_gemm, split, rollout.
// ---------------------------------------------------------------------------
extern "C" void kernel_launch(void* const* d_in, const int* in_sizes, int n_in,
                              void* d_out, int out_size) {
    const float *ctx = nullptr, *Wih = nullptr, *Whh = nullptr,
                *bih = nullptr, *bhh = nullptr, *Whead = nullptr, *bhead = nullptr;
    int b3_seen = 0;
    for (int i = 0; i < n_in; i++) {
        long sz = in_sizes[i];
        const float* p = (const float*)d_in[i];
        if (sz == (long)BB * HH) ctx = p;
        else if (sz == (long)G3 * II) Wih = p;
        else if (sz == (long)G3 * HH) Whh = p;
        else if (sz == (long)G3) { if (b3_seen++ == 0) bih = p; else bhh = p; }
        else if (sz == (long)II * HH) Whead = p;
        else if (sz == (long)II) bhead = p;
    }
    float* out = (float*)d_out;

    cudaFuncSetAttribute(rollout, cudaFuncAttributeMaxDynamicSharedMemorySize, SMEM_DYN);

    init_state<<<(BB * HH + 255) / 256, 256>>>(ctx);
    build_bias<<<NG / 256, 256>>>(Wih, bih, bhh, bhead);
    assemble_w<<<512, 256>>>(Whh, Whead);
    wc_gemm<<<dim3(KK / 64, G3 / 64), 256>>>(Wih, Whh, Whead);
    split_w<<<1024, 256>>>();
    rollout<<<NCTAS, TPB, SMEM_DYN>>>(out, ctx, bhead);

    (void)out_size;
    (void)n_in;
}

// round 8
// speedup vs baseline: 5.7160x; 1.0139x over previous
#include <cuda_runtime.h>
#include <cuda_fp16.h>
#include <cstdint>

// Shapes fixed by the reference.
#define BB 512     // batch
#define HH 1024    // hidden
#define II 256     // input / output feature
#define LL 256     // rollout length
#define G3 3072    // 3*HH
#define NG 4096    // gate GEMM output width (4*HH)
#define N5 4352    // NG + II (appended W_head rows -> y)
#define KK 1024    // GEMM K
#define NCTAS 136  // 4 m-tiles x 34 n-tiles (128x128)
#define TPB 256

#define KC 64                    // fp16 K elements per chunk (128 bytes/row)
#define NCHUNK (KK / KC)         // 16
#define ROWB 144                 // padded smem row bytes (128 + 16)
#define BUFB (128 * ROWB)        // 18432 B per 128x64 fp16 tile
#define STAGE_BYTES (2 * BUFB)   // A, W
#define NSTG 3
#define SMEM_DYN (NSTG * STAGE_BYTES)

typedef __half fp16;

// ---------------------------------------------------------------------------
// Static device scratch.
// ---------------------------------------------------------------------------
__device__ fp16  g_hb[BB * HH];         // fp16 hidden state (GEMM input)
__device__ float g_W5[N5 * KK];         // folded weights (fp32, gate-major)
__device__ float g_W50[N5 * KK];        // step-0 folded weights (gate-major)
__device__ fp16  g_Wf[N5 * KK];         // fp16 weights, 16j-interleaved layout
__device__ fp16  g_W0f[N5 * KK];        // fp16 step-0 weights, interleaved
__device__ float g_b5[NG];              // biases (gate-major layout)
__device__ float g_b50[NG];
__device__ unsigned g_bar;

// ---------------------------------------------------------------------------
// PTX helpers (base ISA, valid on compute_103)
// ---------------------------------------------------------------------------
__device__ __forceinline__ uint32_t smem_u32(const void* p) {
    uint32_t a;
    asm("{ .reg .u64 t; cvta.to.shared.u64 t, %1; cvt.u32.u64 %0, t; }" : "=r"(a) : "l"(p));
    return a;
}
__device__ __forceinline__ void ldsm_x4(uint32_t* r, uint32_t addr) {
    asm volatile("ldmatrix.sync.aligned.m8n8.x4.shared.b16 {%0,%1,%2,%3}, [%4];"
                 : "=r"(r[0]), "=r"(r[1]), "=r"(r[2]), "=r"(r[3]) : "r"(addr));
}
__device__ __forceinline__ void mma_fp16(float* d, const uint32_t* a,
                                         uint32_t b0, uint32_t b1) {
    asm volatile(
        "mma.sync.aligned.m16n8k16.row.col.f32.f16.f16.f32 "
        "{%0,%1,%2,%3}, {%4,%5,%6,%7}, {%8,%9}, {%0,%1,%2,%3};"
        : "+f"(d[0]), "+f"(d[1]), "+f"(d[2]), "+f"(d[3])
        : "r"(a[0]), "r"(a[1]), "r"(a[2]), "r"(a[3]), "r"(b0), "r"(b1));
}
#define CP_ASYNC16(smem, gptr) \
    asm volatile("cp.async.cg.shared.global [%0], [%1], 16;" :: "r"(smem), "l"(gptr))
#define CP_COMMIT() asm volatile("cp.async.commit_group;" ::: "memory")
template <int N>
__device__ __forceinline__ void cp_wait() {
    asm volatile("cp.async.wait_group %0;" :: "n"(N) : "memory");
}
__device__ __forceinline__ float fsigmoid(float x) {
    return 1.0f / (1.0f + __expf(-x));
}

// ---------------------------------------------------------------------------
// Setup kernels
// ---------------------------------------------------------------------------
__global__ void init_state(const float* __restrict__ ctx) {
    int i = blockIdx.x * blockDim.x + threadIdx.x;
    if (i < BB * HH) g_hb[i] = __float2half(ctx[i]);
    if (i == 0) g_bar = 0u;
}

__global__ void build_bias(const float* __restrict__ Wih,
                           const float* __restrict__ bih,
                           const float* __restrict__ bhh,
                           const float* __restrict__ bhead) {
    int j = blockIdx.x * blockDim.x + threadIdx.x;
    if (j >= NG) return;
    float v0, v1;
    if (j < 2048)      v0 = bih[j] + bhh[j];
    else if (j < G3)   v0 = bih[j];
    else               v0 = bhh[j - 1024];
    if (j < G3) {
        float d = 0.0f;
        const float* wr = Wih + (size_t)j * II;
        for (int i = 0; i < II; ++i) d += wr[i] * bhead[i];
        float bc = bih[j] + d;
        v1 = (j < 2048) ? (bhh[j] + bc) : bc;
    } else {
        v1 = bhh[j - 1024];
    }
    g_b50[j] = v0;
    g_b5[j]  = v1;
}

__global__ void assemble_w(const float* __restrict__ Whh,
                           const float* __restrict__ Whead) {
    for (int idx = blockIdx.x * blockDim.x + threadIdx.x;
         idx < N5 * KK; idx += gridDim.x * blockDim.x) {
        int n = idx >> 10;
        float v;
        if (n < 2048)      v = Whh[idx];
        else if (n < G3)   v = 0.0f;
        else if (n < NG)   v = Whh[idx - 1024 * KK];
        else               v = Whead[idx - NG * KK];
        g_W50[idx] = v;
        if (n >= G3) g_W5[idx] = v;
    }
}

__global__ void __launch_bounds__(256)
wc_gemm(const float* __restrict__ Wih,
        const float* __restrict__ Whh,
        const float* __restrict__ Whead) {
    __shared__ __align__(16) float As[16][68];
    __shared__ __align__(16) float Bs[16][68];
    const int tid = threadIdx.x;
    const int n0 = blockIdx.y * 64;
    const int k0 = blockIdx.x * 64;
    const int ty = tid >> 4, tx = tid & 15;

    float acc[4][4] = {};
    for (int i0 = 0; i0 < II; i0 += 16) {
        {
            int row = tid >> 2, ic = (tid & 3) * 4;
            float4 av = *reinterpret_cast<const float4*>(Wih + (size_t)(n0 + row) * II + i0 + ic);
            As[ic + 0][row] = av.x; As[ic + 1][row] = av.y;
            As[ic + 2][row] = av.z; As[ic + 3][row] = av.w;
        }
        {
            int r = tid >> 4, kc = (tid & 15) * 4;
            float4 bv = *reinterpret_cast<const float4*>(Whead + (size_t)(i0 + r) * KK + k0 + kc);
            *reinterpret_cast<float4*>(&Bs[r][kc]) = bv;
        }
        __syncthreads();
#pragma unroll
        for (int i = 0; i < 16; ++i) {
            float a[4], b[4];
#pragma unroll
            for (int u = 0; u < 4; ++u) a[u] = As[i][ty * 4 + u];
#pragma unroll
            for (int u = 0; u < 4; ++u) b[u] = Bs[i][tx * 4 + u];
#pragma unroll
            for (int r = 0; r < 4; ++r)
#pragma unroll
                for (int c = 0; c < 4; ++c) acc[r][c] = fmaf(a[r], b[c], acc[r][c]);
        }
        __syncthreads();
    }
#pragma unroll
    for (int r = 0; r < 4; ++r) {
        int n = n0 + ty * 4 + r;
#pragma unroll
        for (int c = 0; c < 4; ++c) {
            int k = k0 + tx * 4 + c;
            float w = acc[r][c];
            if (n < 2048) w += Whh[(size_t)n * KK + k];
            g_W5[(size_t)n * KK + k] = w;
        }
    }
}

// Permute gate rows into 16j-interleaved layout + convert to fp16.
// old row o = g*1024 + j (g<4)  ->  new row = (j/16)*64 + g*16 + (j%16)
// y rows (o >= 4096) stay in place.
__global__ void split_w() {
    for (int idx = blockIdx.x * blockDim.x + threadIdx.x;
         idx < N5 * KK; idx += gridDim.x * blockDim.x) {
        int o = idx >> 10;
        int k = idx & 1023;
        int nrow;
        if (o < NG) {
            int g = o >> 10;
            int j = o & 1023;
            nrow = (j >> 4) * 64 + g * 16 + (j & 15);
        } else {
            nrow = o;
        }
        size_t dst = (size_t)nrow * KK + k;
        g_Wf[dst]  = __float2half(g_W5[idx]);
        g_W0f[dst] = __float2half(g_W50[idx]);
    }
}

// ---------------------------------------------------------------------------
// Grid barrier (all NCTAS co-resident: 136 <= 148 SMs).
// ---------------------------------------------------------------------------
__device__ __forceinline__ void grid_barrier(unsigned& phase) {
    __threadfence();
    __syncthreads();
    phase += NCTAS;
    if (threadIdx.x == 0) {
        atomicAdd(&g_bar, 1u);
        while (*(volatile unsigned*)&g_bar < phase) { }
        __threadfence();
    }
    __syncthreads();
}

// ---------------------------------------------------------------------------
// Persistent rollout. Warp grid 4m x 2n (32x64 warp tiles), gates fully
// register-local thanks to the 16j gate interleave. Single fp16 h.
// ---------------------------------------------------------------------------
__global__ void __launch_bounds__(TPB, 1)
rollout(float* __restrict__ out, const float* __restrict__ ctx,
        const float* __restrict__ b_head) {
    extern __shared__ __align__(128) char smem[];
    __shared__ float s_b5[128], s_b50[128];
    const uint32_t sm0 = smem_u32(smem);

    const int tid = threadIdx.x;
    const int lane = tid & 31;
    const int wid = tid >> 5;
    const int wm = wid & 3;              // rows 32*wm .. +31
    const int wn = wid >> 2;             // cols 64*wn .. +63
    const int cta = blockIdx.x;
    const int m0 = (cta & 3) * 128;
    const int nt = cta >> 2;             // 0..33
    const bool is_y = (nt >= 32);

    // Per-CTA bias staging. For gate tiles, s_b5[c] matches the interleaved
    // column c = 64*(j/16) + 16*g + (j%16) within this nt's 32 j's.
    if (tid < 128) {
        if (!is_y) {
            int g = (tid & 63) >> 4;
            int jl = (tid >> 6) * 16 + (tid & 15);
            s_b5[tid]  = g_b5[g * 1024 + 32 * nt + jl];
            s_b50[tid] = g_b50[g * 1024 + 32 * nt + jl];
        } else {
            s_b5[tid] = __ldg(b_head + (nt - 32) * 128 + tid);
        }
    }
    __syncthreads();

    const int jc = 2 * (lane & 3);
    const int rq = lane >> 2;

    // Register-resident fp32 h_old: [mt][rs][h8][e] -> 16 values.
    float ho[16];
    if (!is_y) {
#pragma unroll
        for (int mt = 0; mt < 2; ++mt)
#pragma unroll
            for (int rs = 0; rs < 2; ++rs)
#pragma unroll
                for (int h8 = 0; h8 < 2; ++h8)
#pragma unroll
                    for (int e = 0; e < 2; ++e) {
                        int row = m0 + 32 * wm + 16 * mt + 8 * rs + rq;
                        int j = 32 * nt + 16 * wn + 8 * h8 + jc + e;
                        ho[((mt * 2 + rs) * 2 + h8) * 2 + e] =
                            ctx[(size_t)row * HH + j];
                    }
    }

    const uint32_t lm = (uint32_t)(lane & 15) * ROWB + (uint32_t)(lane >> 4) * 16;
    const fp16* Am = g_hb + (size_t)m0 * KK;

    unsigned gphase = 0;

    for (int t = 0; t <= LL; ++t) {
        const bool active = (t < LL) ? !(t == 0 && is_y) : is_y;
        if (active) {
            const fp16* Bw = ((t == 0) ? g_W0f : g_Wf) + (size_t)(nt * 128) * KK;

            float acc[2][8][4];
#pragma unroll
            for (int i = 0; i < 2; ++i)
#pragma unroll
                for (int j = 0; j < 8; ++j)
#pragma unroll
                    for (int k = 0; k < 4; ++k) acc[i][j][k] = 0.0f;

            auto load_chunk = [&](int chunk, int sbuf) {
                const uint32_t sb = sm0 + sbuf * STAGE_BYTES;
                const int kc0 = chunk * KC;
#pragma unroll
                for (int p = 0; p < 4; ++p) {
                    const int s = tid + 256 * p;
                    const int row = s >> 3;
                    const int cs = s & 7;
                    const uint32_t soff = (uint32_t)row * ROWB + (uint32_t)cs * 16;
                    const size_t goff = (size_t)row * KK + kc0 + cs * 8;
                    CP_ASYNC16(sb + 0 * BUFB + soff, Am + goff);
                    CP_ASYNC16(sb + 1 * BUFB + soff, Bw + goff);
                }
                CP_COMMIT();
            };

            load_chunk(0, 0);
            load_chunk(1, 1);

            int sbuf = 0;
            for (int c = 0; c < NCHUNK; ++c) {
                if (c + 1 < NCHUNK) cp_wait<1>(); else cp_wait<0>();
                __syncthreads();
                if (c + 2 < NCHUNK) {
                    int ns = sbuf + 2; if (ns >= NSTG) ns -= NSTG;
                    load_chunk(c + 2, ns);
                }

                const uint32_t sb = sm0 + sbuf * STAGE_BYTES;
                const uint32_t abase = sb + (uint32_t)(32 * wm) * ROWB + lm;
                const uint32_t bbase = sb + BUFB + (uint32_t)(64 * wn) * ROWB + lm;
#pragma unroll
                for (int ks = 0; ks < 4; ++ks) {
                    const uint32_t ko = (uint32_t)ks * 32;
                    uint32_t ah0[4], ah1[4];
                    ldsm_x4(ah0, abase + ko);
                    ldsm_x4(ah1, abase + (uint32_t)(16 * ROWB) + ko);
#pragma unroll
                    for (int u = 0; u < 4; ++u) {
                        uint32_t bb[4];
                        ldsm_x4(bb, bbase + (uint32_t)(16 * u) * ROWB + ko);
                        mma_fp16(acc[0][2 * u + 0], ah0, bb[0], bb[2]);
                        mma_fp16(acc[0][2 * u + 1], ah0, bb[1], bb[3]);
                        mma_fp16(acc[1][2 * u + 0], ah1, bb[0], bb[2]);
                        mma_fp16(acc[1][2 * u + 1], ah1, bb[1], bb[3]);
                    }
                }
                if (++sbuf == NSTG) sbuf = 0;
            }

            // ---- fused epilogue ----
            if (!is_y) {
                const float* sb2 = (t == 0) ? s_b50 : s_b5;
#pragma unroll
                for (int mt = 0; mt < 2; ++mt)
#pragma unroll
                    for (int rs = 0; rs < 2; ++rs) {
                        const int row = m0 + 32 * wm + 16 * mt + 8 * rs + rq;
#pragma unroll
                        for (int h8 = 0; h8 < 2; ++h8) {
                            float hn[2];
#pragma unroll
                            for (int e = 0; e < 2; ++e) {
                                const int cb = 64 * wn + 8 * h8 + jc + e;
                                float rp = acc[mt][0 + h8][2 * rs + e] + sb2[cb];
                                float zp = acc[mt][2 + h8][2 * rs + e] + sb2[cb + 16];
                                float gn = acc[mt][4 + h8][2 * rs + e] + sb2[cb + 32];
                                float gh = acc[mt][6 + h8][2 * rs + e] + sb2[cb + 48];
                                float r = fsigmoid(rp);
                                float z = fsigmoid(zp);
                                float nn = tanhf(gn + r * gh);
                                const int ii = ((mt * 2 + rs) * 2 + h8) * 2 + e;
                                float hnew = (1.0f - z) * nn + z * ho[ii];
                                ho[ii] = hnew;
                                hn[e] = hnew;
                            }
                            const int jb = 32 * nt + 16 * wn + 8 * h8 + jc;
                            *reinterpret_cast<__half2*>(g_hb + (size_t)row * HH + jb) =
                                __floats2half2_rn(hn[0], hn[1]);
                        }
                    }
            } else {
                float* yb = out + (size_t)(t - 1) * BB * II;
#pragma unroll
                for (int mt = 0; mt < 2; ++mt)
#pragma unroll
                    for (int rs = 0; rs < 2; ++rs) {
                        const int row = m0 + 32 * wm + 16 * mt + 8 * rs + rq;
#pragma unroll
                        for (int f = 0; f < 8; ++f) {
                            const int ci = 64 * wn + 8 * f + jc;
                            const int col = (nt - 32) * 128 + ci;
                            float2 v = make_float2(acc[mt][f][2 * rs + 0] + s_b5[ci],
                                                   acc[mt][f][2 * rs + 1] + s_b5[ci + 1]);
                            *reinterpret_cast<float2*>(yb + (size_t)row * II + col) = v;
                        }
                    }
            }
        }

        if (t == LL) break;
        grid_barrier(gphase);
    }
}

// ---------------------------------------------------------------------------
// 6 graph nodes: init, bias, assemble, wc_gemm, split, rollout.
// ---------------------------------------------------------------------------
extern "C" void kernel_launch(void* const* d_in, const int* in_sizes, int n_in,
                              void* d_out, int out_size) {
    const float *ctx = nullptr, *Wih = nullptr, *Whh = nullptr,
                *bih = nullptr, *bhh = nullptr, *Whead = nullptr, *bhead = nullptr;
    int b3_seen = 0;
    for (int i = 0; i < n_in; i++) {
        long sz = in_sizes[i];
        const float* p = (const float*)d_in[i];
        if (sz == (long)BB * HH) ctx = p;
        else if (sz == (long)G3 * II) Wih = p;
        else if (sz == (long)G3 * HH) Whh = p;
        else if (sz == (long)G3) { if (b3_seen++ == 0) bih = p; else bhh = p; }
        else if (sz == (long)II * HH) Whead = p;
        else if (sz == (long)II) bhead = p;
    }
    float* out = (float*)d_out;

    cudaFuncSetAttribute(rollout, cudaFuncAttributeMaxDynamicSharedMemorySize, SMEM_DYN);

    init_state<<<(BB * HH + 255) / 256, 256>>>(ctx);
    build_bias<<<NG / 256, 256>>>(Wih, bih, bhh, bhead);
    assemble_w<<<512, 256>>>(Whh, Whead);
    wc_gemm<<<dim3(KK / 64, G3 / 64), 256>>>(Wih, Whh, Whead);
    split_w<<<1024, 256>>>();
    rollout<<<NCTAS, TPB, SMEM_DYN>>>(out, ctx, bhead);

    (void)out_size;
    (void)n_in;
}

// round 9
// speedup vs baseline: 6.4115x; 1.1217x over previous
#include <cuda_runtime.h>
#include <cuda_fp16.h>
#include <cstdint>

// Shapes fixed by the reference.
#define BB 512     // batch
#define HH 1024    // hidden
#define II 256     // input / output feature
#define LL 256     // rollout length
#define G3 3072    // 3*HH
#define NG 4096    // gate GEMM output width (4*HH)
#define N5 4352    // NG + II (appended W_head rows -> y)
#define KK 1024    // GEMM K
#define NCTAS 136  // 4 m-tiles x 34 n-tiles (128x128)
#define GROUP 34   // CTAs per independent m-row group
#define TPB 256

#define KC 128                   // fp16 K elements per chunk (256 bytes/row)
#define NCHUNK (KK / KC)         // 8
#define ROWB 272                 // padded smem row bytes (256 + 16)
#define BUFB (128 * ROWB)        // 34816 B per 128x128 fp16 tile
#define STAGE_BYTES (2 * BUFB)   // A, B
#define NSTG 2
#define SMEM_DYN (NSTG * STAGE_BYTES)   // 139264 B

typedef __half fp16;

// ---------------------------------------------------------------------------
// Static device scratch.
// ---------------------------------------------------------------------------
__device__ fp16  g_hb[BB * HH];         // fp16 hidden state (GEMM input)
__device__ fp16  g_Wf[N5 * KK];         // fp16 weights, 16j-interleaved
__device__ fp16  g_W0f[N5 * KK];        // fp16 step-0 weights, interleaved
__device__ float g_b5[NG];              // biases (gate-major layout)
__device__ float g_b50[NG];
__device__ unsigned g_bar4[4 * 32];     // per-m-row barrier counters (128B apart)

// ---------------------------------------------------------------------------
// PTX helpers (base ISA, valid on compute_103)
// ---------------------------------------------------------------------------
__device__ __forceinline__ uint32_t smem_u32(const void* p) {
    uint32_t a;
    asm("{ .reg .u64 t; cvta.to.shared.u64 t, %1; cvt.u32.u64 %0, t; }" : "=r"(a) : "l"(p));
    return a;
}
__device__ __forceinline__ void ldsm_x4(uint32_t* r, uint32_t addr) {
    asm volatile("ldmatrix.sync.aligned.m8n8.x4.shared.b16 {%0,%1,%2,%3}, [%4];"
                 : "=r"(r[0]), "=r"(r[1]), "=r"(r[2]), "=r"(r[3]) : "r"(addr));
}
__device__ __forceinline__ void mma_fp16(float* d, const uint32_t* a,
                                         uint32_t b0, uint32_t b1) {
    asm volatile(
        "mma.sync.aligned.m16n8k16.row.col.f32.f16.f16.f32 "
        "{%0,%1,%2,%3}, {%4,%5,%6,%7}, {%8,%9}, {%0,%1,%2,%3};"
        : "+f"(d[0]), "+f"(d[1]), "+f"(d[2]), "+f"(d[3])
        : "r"(a[0]), "r"(a[1]), "r"(a[2]), "r"(a[3]), "r"(b0), "r"(b1));
}
#define CP_ASYNC16(smem, gptr) \
    asm volatile("cp.async.cg.shared.global [%0], [%1], 16;" :: "r"(smem), "l"(gptr))
#define CP_COMMIT() asm volatile("cp.async.commit_group;" ::: "memory")
template <int N>
__device__ __forceinline__ void cp_wait() {
    asm volatile("cp.async.wait_group %0;" :: "n"(N) : "memory");
}
__device__ __forceinline__ float fsigmoid(float x) {
    return __fdividef(1.0f, 1.0f + __expf(-x));
}
__device__ __forceinline__ float ftanh(float x) {
    float e = __expf(2.0f * x);
    return 1.0f - __fdividef(2.0f, e + 1.0f);
}

// Interleaved row for gate row (g, j): (j/16)*64 + g*16 + (j%16)
__device__ __forceinline__ int irow(int g, int j) {
    return ((j >> 4) << 6) + (g << 4) + (j & 15);
}

// ---------------------------------------------------------------------------
// Setup kernels
// ---------------------------------------------------------------------------
__global__ void init_state(const float* __restrict__ ctx) {
    int i = blockIdx.x * blockDim.x + threadIdx.x;
    if (i < BB * HH) g_hb[i] = __float2half(ctx[i]);
    if (i < 4 * 32) g_bar4[i] = 0u;
}

__global__ void build_bias(const float* __restrict__ Wih,
                           const float* __restrict__ bih,
                           const float* __restrict__ bhh,
                           const float* __restrict__ bhead) {
    int j = blockIdx.x * blockDim.x + threadIdx.x;
    if (j >= NG) return;
    float v0, v1;
    if (j < 2048)      v0 = bih[j] + bhh[j];
    else if (j < G3)   v0 = bih[j];
    else               v0 = bhh[j - 1024];
    if (j < G3) {
        float d = 0.0f;
        const float* wr = Wih + (size_t)j * II;
        for (int i = 0; i < II; ++i) d += wr[i] * bhead[i];
        float bc = bih[j] + d;
        v1 = (j < 2048) ? (bhh[j] + bc) : bc;
    } else {
        v1 = bhh[j - 1024];
    }
    g_b50[j] = v0;
    g_b5[j]  = v1;
}

// Rows n in [3072, 4352): ghn block (Whh_n) and y block (Whead).
// Same values in g_Wf and g_W0f.
__global__ void copy_rest(const float* __restrict__ Whh,
                          const float* __restrict__ Whead) {
    for (int idx = blockIdx.x * blockDim.x + threadIdx.x;
         idx < (N5 - G3) * KK; idx += gridDim.x * blockDim.x) {
        int o = G3 + (idx >> 10);
        int k = idx & 1023;
        int nrow;
        float v;
        if (o < NG) {
            int j = o - G3;
            nrow = irow(3, j);
            v = Whh[(size_t)(o - 1024) * KK + k];
        } else {
            nrow = o;
            v = Whead[(size_t)(o - NG) * KK + k];
        }
        fp16 h = __float2half(v);
        g_Wf[(size_t)nrow * KK + k]  = h;
        g_W0f[(size_t)nrow * KK + k] = h;
    }
}

// Wc = W_ih @ W_head for rows n < 3072; writes fp16 interleaved weights
// directly:  g_Wf[irow] = Wc + (n<2048 ? Whh : 0),
//            g_W0f[irow] = (n<2048 ? Whh : 0).
__global__ void __launch_bounds__(256)
wc_gemm(const float* __restrict__ Wih,
        const float* __restrict__ Whh,
        const float* __restrict__ Whead) {
    __shared__ __align__(16) float As[16][68];
    __shared__ __align__(16) float Bs[16][68];
    const int tid = threadIdx.x;
    const int n0 = blockIdx.y * 64;
    const int k0 = blockIdx.x * 64;
    const int ty = tid >> 4, tx = tid & 15;

    float acc[4][4] = {};
    for (int i0 = 0; i0 < II; i0 += 16) {
        {
            int row = tid >> 2, ic = (tid & 3) * 4;
            float4 av = *reinterpret_cast<const float4*>(Wih + (size_t)(n0 + row) * II + i0 + ic);
            As[ic + 0][row] = av.x; As[ic + 1][row] = av.y;
            As[ic + 2][row] = av.z; As[ic + 3][row] = av.w;
        }
        {
            int r = tid >> 4, kc = (tid & 15) * 4;
            float4 bv = *reinterpret_cast<const float4*>(Whead + (size_t)(i0 + r) * KK + k0 + kc);
            *reinterpret_cast<float4*>(&Bs[r][kc]) = bv;
        }
        __syncthreads();
#pragma unroll
        for (int i = 0; i < 16; ++i) {
            float a[4], b[4];
#pragma unroll
            for (int u = 0; u < 4; ++u) a[u] = As[i][ty * 4 + u];
#pragma unroll
            for (int u = 0; u < 4; ++u) b[u] = Bs[i][tx * 4 + u];
#pragma unroll
            for (int r = 0; r < 4; ++r)
#pragma unroll
                for (int c = 0; c < 4; ++c) acc[r][c] = fmaf(a[r], b[c], acc[r][c]);
        }
        __syncthreads();
    }
#pragma unroll
    for (int r = 0; r < 4; ++r) {
        int n = n0 + ty * 4 + r;
        int g = n >> 10;
        int j = n & 1023;
        size_t nr = (size_t)irow(g, j) * KK;
#pragma unroll
        for (int c = 0; c < 4; ++c) {
            int k = k0 + tx * 4 + c;
            float base = (n < 2048) ? Whh[(size_t)n * KK + k] : 0.0f;
            g_Wf[nr + k]  = __float2half(acc[r][c] + base);
            g_W0f[nr + k] = __float2half(base);
        }
    }
}

// ---------------------------------------------------------------------------
// Per-m-row barrier: 34 CTAs of one m-row group.
// ---------------------------------------------------------------------------
__device__ __forceinline__ void row_barrier(int mrow, unsigned& phase) {
    __threadfence();
    __syncthreads();
    phase += GROUP;
    if (threadIdx.x == 0) {
        atomicAdd(&g_bar4[mrow * 32], 1u);
        while (*(volatile unsigned*)&g_bar4[mrow * 32] < phase) { }
        __threadfence();
    }
    __syncthreads();
}

// ---------------------------------------------------------------------------
// Persistent rollout. Warp grid 4m x 2n (32x64 warp tiles), gates fully
// register-local (16j interleave). Single fp16 h. 2-stage KC=128 pipeline;
// B chunk 0 prefetched across the barrier (weights are static).
// ---------------------------------------------------------------------------
__global__ void __launch_bounds__(TPB, 1)
rollout(float* __restrict__ out, const float* __restrict__ ctx,
        const float* __restrict__ b_head) {
    extern __shared__ __align__(128) char smem[];
    __shared__ float s_b5[128], s_b50[128];
    const uint32_t sm0 = smem_u32(smem);

    const int tid = threadIdx.x;
    const int lane = tid & 31;
    const int wid = tid >> 5;
    const int wm = wid & 3;              // rows 32*wm .. +31
    const int wn = wid >> 2;             // cols 64*wn .. +63
    const int cta = blockIdx.x;
    const int mrow = cta & 3;
    const int m0 = mrow * 128;
    const int nt = cta >> 2;             // 0..33
    const bool is_y = (nt >= 32);

    // Per-CTA bias staging (interleaved col c = 64*(j/16) + 16*g + (j%16)).
    if (tid < 128) {
        if (!is_y) {
            int g = (tid & 63) >> 4;
            int jl = (tid >> 6) * 16 + (tid & 15);
            s_b5[tid]  = g_b5[g * 1024 + 32 * nt + jl];
            s_b50[tid] = g_b50[g * 1024 + 32 * nt + jl];
        } else {
            s_b5[tid] = __ldg(b_head + (nt - 32) * 128 + tid);
        }
    }
    __syncthreads();

    const int jc = 2 * (lane & 3);
    const int rq = lane >> 2;

    // Register-resident fp32 h_old: [mt][rs][h8][e] -> 16 values.
    float ho[16];
    if (!is_y) {
#pragma unroll
        for (int mt = 0; mt < 2; ++mt)
#pragma unroll
            for (int rs = 0; rs < 2; ++rs)
#pragma unroll
                for (int h8 = 0; h8 < 2; ++h8)
#pragma unroll
                    for (int e = 0; e < 2; ++e) {
                        int row = m0 + 32 * wm + 16 * mt + 8 * rs + rq;
                        int j = 32 * nt + 16 * wn + 8 * h8 + jc + e;
                        ho[((mt * 2 + rs) * 2 + h8) * 2 + e] =
                            ctx[(size_t)row * HH + j];
                    }
    }

    const uint32_t lm = (uint32_t)(lane & 15) * ROWB + (uint32_t)(lane >> 4) * 16;
    const fp16* Am = g_hb + (size_t)m0 * KK;

    // Loaders: 2048 16B segments per 128x128 tile -> 8 per thread.
    auto load_B = [&](int chunk, int sbuf, const fp16* Bw) {
        const uint32_t sb = sm0 + sbuf * STAGE_BYTES + BUFB;
        const int kc0 = chunk * KC;
#pragma unroll
        for (int p = 0; p < 8; ++p) {
            const int s = tid + 256 * p;
            const int row = s >> 4;
            const int cs = s & 15;
            CP_ASYNC16(sb + (uint32_t)row * ROWB + (uint32_t)cs * 16,
                       Bw + (size_t)row * KK + kc0 + cs * 8);
        }
        CP_COMMIT();
    };
    auto load_A = [&](int chunk, int sbuf) {
        const uint32_t sb = sm0 + sbuf * STAGE_BYTES;
        const int kc0 = chunk * KC;
#pragma unroll
        for (int p = 0; p < 8; ++p) {
            const int s = tid + 256 * p;
            const int row = s >> 4;
            const int cs = s & 15;
            CP_ASYNC16(sb + (uint32_t)row * ROWB + (uint32_t)cs * 16,
                       Am + (size_t)row * KK + kc0 + cs * 8);
        }
        CP_COMMIT();
    };
    auto load_AB = [&](int chunk, int sbuf, const fp16* Bw) {
        const uint32_t sa = sm0 + sbuf * STAGE_BYTES;
        const int kc0 = chunk * KC;
#pragma unroll
        for (int p = 0; p < 8; ++p) {
            const int s = tid + 256 * p;
            const int row = s >> 4;
            const int cs = s & 15;
            const uint32_t soff = (uint32_t)row * ROWB + (uint32_t)cs * 16;
            const size_t goff = (size_t)row * KK + kc0 + cs * 8;
            CP_ASYNC16(sa + soff, Am + goff);
            CP_ASYNC16(sa + BUFB + soff, Bw + goff);
        }
        CP_COMMIT();
    };

    unsigned gphase = 0;

    // Pre-loop B prefetch for t=0 (gate CTAs are active at t=0).
    if (!is_y) load_B(0, 0, g_W0f + (size_t)(nt * 128) * KK);

    for (int t = 0; t <= LL; ++t) {
        const bool active = (t < LL) ? !(t == 0 && is_y) : is_y;
        if (active) {
            const fp16* Bw = ((t == 0) ? g_W0f : g_Wf) + (size_t)(nt * 128) * KK;

            float acc[2][8][4];
#pragma unroll
            for (int i = 0; i < 2; ++i)
#pragma unroll
                for (int j = 0; j < 8; ++j)
#pragma unroll
                    for (int k = 0; k < 4; ++k) acc[i][j][k] = 0.0f;

            load_A(0, 0);          // B chunk 0 already prefetched pre-barrier

            for (int c = 0; c < NCHUNK; ++c) {
                const int sbuf = c & 1;
                if (c + 1 < NCHUNK) {
                    load_AB(c + 1, sbuf ^ 1, Bw);
                    cp_wait<1>();
                } else {
                    cp_wait<0>();
                }
                __syncthreads();

                const uint32_t sb = sm0 + sbuf * STAGE_BYTES;
                const uint32_t abase = sb + (uint32_t)(32 * wm) * ROWB + lm;
                const uint32_t bbase = sb + BUFB + (uint32_t)(64 * wn) * ROWB + lm;
#pragma unroll
                for (int ks = 0; ks < 8; ++ks) {
                    const uint32_t ko = (uint32_t)ks * 32;
                    uint32_t ah0[4], ah1[4];
                    ldsm_x4(ah0, abase + ko);
                    ldsm_x4(ah1, abase + (uint32_t)(16 * ROWB) + ko);
#pragma unroll
                    for (int u = 0; u < 4; ++u) {
                        uint32_t bb[4];
                        ldsm_x4(bb, bbase + (uint32_t)(16 * u) * ROWB + ko);
                        mma_fp16(acc[0][2 * u + 0], ah0, bb[0], bb[2]);
                        mma_fp16(acc[0][2 * u + 1], ah0, bb[1], bb[3]);
                        mma_fp16(acc[1][2 * u + 0], ah1, bb[0], bb[2]);
                        mma_fp16(acc[1][2 * u + 1], ah1, bb[1], bb[3]);
                    }
                }
                __syncthreads();
            }

            // ---- fused epilogue ----
            if (!is_y) {
                const float* sb2 = (t == 0) ? s_b50 : s_b5;
#pragma unroll
                for (int mt = 0; mt < 2; ++mt)
#pragma unroll
                    for (int rs = 0; rs < 2; ++rs) {
                        const int row = m0 + 32 * wm + 16 * mt + 8 * rs + rq;
#pragma unroll
                        for (int h8 = 0; h8 < 2; ++h8) {
                            float hn[2];
#pragma unroll
                            for (int e = 0; e < 2; ++e) {
                                const int cb = 64 * wn + 8 * h8 + jc + e;
                                float rp = acc[mt][0 + h8][2 * rs + e] + sb2[cb];
                                float zp = acc[mt][2 + h8][2 * rs + e] + sb2[cb + 16];
                                float gn = acc[mt][4 + h8][2 * rs + e] + sb2[cb + 32];
                                float gh = acc[mt][6 + h8][2 * rs + e] + sb2[cb + 48];
                                float r = fsigmoid(rp);
                                float z = fsigmoid(zp);
                                float nn = ftanh(gn + r * gh);
                                const int ii = ((mt * 2 + rs) * 2 + h8) * 2 + e;
                                float hnew = (1.0f - z) * nn + z * ho[ii];
                                ho[ii] = hnew;
                                hn[e] = hnew;
                            }
                            const int jb = 32 * nt + 16 * wn + 8 * h8 + jc;
                            *reinterpret_cast<__half2*>(g_hb + (size_t)row * HH + jb) =
                                __floats2half2_rn(hn[0], hn[1]);
                        }
                    }
            } else {
                float* yb = out + (size_t)(t - 1) * BB * II;
#pragma unroll
                for (int mt = 0; mt < 2; ++mt)
#pragma unroll
                    for (int rs = 0; rs < 2; ++rs) {
                        const int row = m0 + 32 * wm + 16 * mt + 8 * rs + rq;
#pragma unroll
                        for (int f = 0; f < 8; ++f) {
                            const int ci = 64 * wn + 8 * f + jc;
                            const int col = (nt - 32) * 128 + ci;
                            float2 v = make_float2(acc[mt][f][2 * rs + 0] + s_b5[ci],
                                                   acc[mt][f][2 * rs + 1] + s_b5[ci + 1]);
                            *reinterpret_cast<float2*>(yb + (size_t)row * II + col) = v;
                        }
                    }
            }
        }

        if (t == LL) break;

        // Pre-barrier B prefetch for t+1 (weights are static; safe to load
        // across the barrier). Gate CTAs are inactive at t+1 == LL.
        const bool next_active = is_y ? true : (t + 1 < LL);
        if (next_active) load_B(0, 0, g_Wf + (size_t)(nt * 128) * KK);

        row_barrier(mrow, gphase);
    }
}

// ---------------------------------------------------------------------------
// 5 graph nodes: init, bias, wc_gemm, copy_rest, rollout.
// ---------------------------------------------------------------------------
extern "C" void kernel_launch(void* const* d_in, const int* in_sizes, int n_in,
                              void* d_out, int out_size) {
    const float *ctx = nullptr, *Wih = nullptr, *Whh = nullptr,
                *bih = nullptr, *bhh = nullptr, *Whead = nullptr, *bhead = nullptr;
    int b3_seen = 0;
    for (int i = 0; i < n_in; i++) {
        long sz = in_sizes[i];
        const float* p = (const float*)d_in[i];
        if (sz == (long)BB * HH) ctx = p;
        else if (sz == (long)G3 * II) Wih = p;
        else if (sz == (long)G3 * HH) Whh = p;
        else if (sz == (long)G3) { if (b3_seen++ == 0) bih = p; else bhh = p; }
        else if (sz == (long)II * HH) Whead = p;
        else if (sz == (long)II) bhead = p;
    }
    float* out = (float*)d_out;

    cudaFuncSetAttribute(rollout, cudaFuncAttributeMaxDynamicSharedMemorySize, SMEM_DYN);

    init_state<<<(BB * HH + 255) / 256, 256>>>(ctx);
    build_bias<<<NG / 256, 256>>>(Wih, bih, bhh, bhead);
    wc_gemm<<<dim3(KK / 64, G3 / 64), 256>>>(Wih, Whh, Whead);
    copy_rest<<<640, 256>>>(Whh, Whead);
    rollout<<<NCTAS, TPB, SMEM_DYN>>>(out, ctx, bhead);

    (void)out_size;
    (void)n_in;
}